// round 4
// baseline (speedup 1.0000x reference)
#include <cuda_runtime.h>
#include <math.h>

#define BSZ 2
#define TT 16
#define HH 32
#define WW 32
#define CC 192
#define LL 16384            // TT*HH*WW
#define DI 384
#define DTR 12
#define DST 16
#define NXDB 44             // DTR + 2*DST
#define BL (BSZ*LL)         // 32768
#define EPSV 1e-5f

// ---------------------------------------------------------------------------
// scratch (device globals; no allocation allowed)
// ---------------------------------------------------------------------------
__device__ float  g_w1t[27*CC*CC];
__device__ float  g_w2t[27*CC*CC];
__device__ float  g_y1 [(size_t)BL*CC];
__device__ float  g_y2 [(size_t)BL*CC];
__device__ float  g_xc [(size_t)BL*CC];
__device__ float  g_xn [(size_t)BL*CC];
__device__ float  g_xz [(size_t)BL*2*DI];
__device__ float  g_ua [(size_t)BL*DI];
__device__ float  g_xdb[(size_t)BL*NXDB];
__device__ float  g_dl [(size_t)BL*DI];
__device__ float  g_yy [(size_t)BL*DI];
__device__ float2 g_part[BSZ*128*CC];
__device__ float2 g_p1[BSZ*CC];
__device__ float2 g_p2[BSZ*CC];

__device__ __forceinline__ float softplusf(float v) {
    return v > 20.f ? v : log1pf(__expf(v));
}
__device__ __forceinline__ float siluf(float v) {
    return v / (1.f + __expf(-v));
}

// ---------------------------------------------------------------------------
// weight transpose: (co,ci,dt,dh,dw) -> [tap][ci][co], tap = (dt*3+dh)*3+dw
// ---------------------------------------------------------------------------
__global__ void transpose_w_k(const float* __restrict__ w, float* __restrict__ wt) {
    int idx = blockIdx.x * 256 + threadIdx.x;
    if (idx >= 27*CC*CC) return;
    int co  = idx % CC;
    int ci  = (idx / CC) % CC;
    int tap = idx / (CC*CC);
    wt[idx] = w[((size_t)co*CC + ci)*27 + tap];
}

// ---------------------------------------------------------------------------
// 3D conv (channel-last). One block per (b,t,h): 32 w x 192 co outputs.
// NORM_IN: input element -> leaky(instnorm(v)) using nprm (mean,rstd) per (b,c).
// ---------------------------------------------------------------------------
template<bool NORM_IN>
__global__ __launch_bounds__(256)
void conv3d_k(const float* __restrict__ in, const float* __restrict__ wT,
              const float* __restrict__ bias, const float2* __restrict__ nprm,
              float* __restrict__ out)
{
    __shared__ float in_s[34*CC];   // w = -1..32 (index = w+1), per (dt,dh)
    __shared__ float w_s[24*CC];    // 24 ci x 192 co chunk

    const int tid = threadIdx.x;
    const int h = blockIdx.x, t = blockIdx.y, b = blockIdx.z;
    const int wg = tid >> 5;        // 0..7  -> w = wg*4+iw
    const int cg = tid & 31;        // 0..31 -> co = cg + 32*j

    float acc[4][6];
    #pragma unroll
    for (int i = 0; i < 4; ++i)
        #pragma unroll
        for (int j = 0; j < 6; ++j) acc[i][j] = 0.f;

    for (int dt = 0; dt < 3; ++dt) {
        int ti = t + dt - 1;
        if ((unsigned)ti >= TT) continue;
        for (int dh = 0; dh < 3; ++dh) {
            int hi = h + dh - 1;
            if ((unsigned)hi >= HH) continue;      // block-uniform
            __syncthreads();
            {
                const float* src = in + (((size_t)(b*TT + ti)*HH + hi)*WW)*CC;
                for (int i = tid; i < 34*CC; i += 256) {
                    int pos = i / CC, c = i - pos*CC;
                    int wi = pos - 1;
                    float v = 0.f;
                    if ((unsigned)wi < WW) {
                        v = src[(size_t)wi*CC + c];
                        if (NORM_IN) {
                            float2 p = nprm[b*CC + c];
                            v = (v - p.x) * p.y;
                            v = v >= 0.f ? v : 0.01f*v;
                        }
                    }
                    in_s[i] = v;
                }
            }
            for (int dw = 0; dw < 3; ++dw) {
                const int tap = (dt*3 + dh)*3 + dw;
                const float* wt = wT + (size_t)tap*CC*CC;
                for (int c0 = 0; c0 < CC; c0 += 24) {
                    __syncthreads();
                    for (int i = tid; i < 24*CC; i += 256)
                        w_s[i] = wt[(size_t)c0*CC + i];
                    __syncthreads();
                    #pragma unroll 6
                    for (int ci = 0; ci < 24; ++ci) {
                        float wv[6];
                        #pragma unroll
                        for (int j = 0; j < 6; ++j) wv[j] = w_s[ci*CC + cg + 32*j];
                        #pragma unroll
                        for (int iw = 0; iw < 4; ++iw) {
                            float a = in_s[(wg*4 + iw + dw)*CC + c0 + ci];
                            #pragma unroll
                            for (int j = 0; j < 6; ++j) acc[iw][j] += a * wv[j];
                        }
                    }
                }
            }
        }
    }

    float* dst = out + (((size_t)(b*TT + t)*HH + h)*WW)*CC;
    #pragma unroll
    for (int iw = 0; iw < 4; ++iw) {
        int w = wg*4 + iw;
        #pragma unroll
        for (int j = 0; j < 6; ++j) {
            int co = cg + 32*j;
            dst[(size_t)w*CC + co] = acc[iw][j] + bias[co];
        }
    }
}

// ---------------------------------------------------------------------------
// instance-norm statistics: partial sums then finalize to (mean, rstd)
// ---------------------------------------------------------------------------
__global__ void stat_partial_k(const float* __restrict__ y, float2* __restrict__ part) {
    int b = blockIdx.y, ch = blockIdx.x, c = threadIdx.x;   // 192 threads
    const float* src = y + ((size_t)b*LL + (size_t)ch*128)*CC + c;
    float s = 0.f, q = 0.f;
    for (int l = 0; l < 128; ++l) {
        float v = src[(size_t)l*CC];
        s += v; q += v*v;
    }
    part[((size_t)b*128 + ch)*CC + c] = make_float2(s, q);
}

__global__ void stat_final_k(const float2* __restrict__ part, float2* __restrict__ p) {
    int idx = threadIdx.x;            // 384 = BSZ*CC
    int b = idx / CC, c = idx % CC;
    float s = 0.f, q = 0.f;
    for (int k = 0; k < 128; ++k) {
        float2 v = part[((size_t)b*128 + k)*CC + c];
        s += v.x; q += v.y;
    }
    float mu  = s * (1.f/(float)LL);
    float var = q * (1.f/(float)LL) - mu*mu;
    p[idx] = make_float2(mu, rsqrtf(fmaxf(var, 0.f) + EPSV));
}

// ---------------------------------------------------------------------------
// xc = instnorm2(y2) + residual(x)
// ---------------------------------------------------------------------------
__global__ void apply_nr_k(const float* __restrict__ y2, const float* __restrict__ x,
                           const float2* __restrict__ p, float* __restrict__ xc) {
    size_t i = (size_t)blockIdx.x*256 + threadIdx.x;
    if (i >= (size_t)BL*CC) return;
    int c = (int)(i % CC);
    int b = (int)(i / ((size_t)LL*CC));
    float2 pr = p[b*CC + c];
    xc[i] = (y2[i] - pr.x)*pr.y + x[i];
}

// ---------------------------------------------------------------------------
// LayerNorm over the "reshape" tokens: token (b,l) gathers xc_flat[b][d*LL + l]
// for d=0..191, normalizes over d, writes row-major x_norm[(b*LL+l)*192 + d].
// ---------------------------------------------------------------------------
__global__ __launch_bounds__(256)
void ln_k(const float* __restrict__ xc, const float* __restrict__ g,
          const float* __restrict__ be, float* __restrict__ xn) {
    int l = blockIdx.x*256 + threadIdx.x;
    int b = blockIdx.y;
    const float* base = xc + (size_t)b*LL*CC;
    float s = 0.f, q = 0.f;
    for (int d = 0; d < CC; ++d) {
        float v = base[(size_t)d*LL + l];
        s += v; q += v*v;
    }
    float mu = s * (1.f/(float)CC);
    float rs = rsqrtf(fmaxf(q*(1.f/(float)CC) - mu*mu, 0.f) + EPSV);
    float* o = xn + ((size_t)b*LL + l)*CC;
    for (int d = 0; d < CC; ++d) {
        float v = base[(size_t)d*LL + l];
        o[d] = (v - mu)*rs*g[d] + be[d];
    }
}

// ---------------------------------------------------------------------------
// SGEMM: C[M,N] = A[M,K] @ B[N,K]^T   (B row-major [N,K])
// EPI: 0 = none, 1 = softplus(acc + bias[n])
// BM=BN=64, BK=16, 256 threads, 4x4 per thread.
// ---------------------------------------------------------------------------
template<int EPI>
__global__ __launch_bounds__(256)
void gemm_k(const float* __restrict__ A, int lda,
            const float* __restrict__ Bw, const float* __restrict__ bias,
            float* __restrict__ C, int ldc, int N, int K)
{
    __shared__ __align__(16) float As[16][68];
    __shared__ __align__(16) float Bs[16][68];

    const int tid = threadIdx.x;
    const int n0 = blockIdx.x * 64, m0 = blockIdx.y * 64;
    const int tm = tid >> 4, tn = tid & 15;
    const int lr = tid >> 2;          // 0..63 tile row
    const int lc = (tid & 3) << 2;    // 0,4,8,12 k offset

    float acc[4][4];
    #pragma unroll
    for (int i = 0; i < 4; ++i)
        #pragma unroll
        for (int j = 0; j < 4; ++j) acc[i][j] = 0.f;

    for (int k0 = 0; k0 < K; k0 += 16) {
        float4 av = make_float4(0.f,0.f,0.f,0.f);
        float4 bv = make_float4(0.f,0.f,0.f,0.f);
        if (k0 + lc < K)
            av = *(const float4*)(A + (size_t)(m0 + lr)*lda + k0 + lc);
        if ((n0 + lr) < N && (k0 + lc) < K)
            bv = *(const float4*)(Bw + (size_t)(n0 + lr)*K + k0 + lc);
        __syncthreads();
        As[lc+0][lr]=av.x; As[lc+1][lr]=av.y; As[lc+2][lr]=av.z; As[lc+3][lr]=av.w;
        Bs[lc+0][lr]=bv.x; Bs[lc+1][lr]=bv.y; Bs[lc+2][lr]=bv.z; Bs[lc+3][lr]=bv.w;
        __syncthreads();
        #pragma unroll
        for (int kk = 0; kk < 16; ++kk) {
            float4 ra = *(const float4*)&As[kk][tm*4];
            float4 rb = *(const float4*)&Bs[kk][tn*4];
            acc[0][0] += ra.x*rb.x; acc[0][1] += ra.x*rb.y; acc[0][2] += ra.x*rb.z; acc[0][3] += ra.x*rb.w;
            acc[1][0] += ra.y*rb.x; acc[1][1] += ra.y*rb.y; acc[1][2] += ra.y*rb.z; acc[1][3] += ra.y*rb.w;
            acc[2][0] += ra.z*rb.x; acc[2][1] += ra.z*rb.y; acc[2][2] += ra.z*rb.z; acc[2][3] += ra.z*rb.w;
            acc[3][0] += ra.w*rb.x; acc[3][1] += ra.w*rb.y; acc[3][2] += ra.w*rb.z; acc[3][3] += ra.w*rb.w;
        }
    }

    #pragma unroll
    for (int i = 0; i < 4; ++i) {
        int m = m0 + tm*4 + i;
        #pragma unroll
        for (int j = 0; j < 4; ++j) {
            int n = n0 + tn*4 + j;
            if (n < N) {
                float v = acc[i][j];
                if (EPI == 1) v = softplusf(v + bias[n]);
                C[(size_t)m*ldc + n] = v;
            }
        }
    }
}

// ---------------------------------------------------------------------------
// causal depthwise conv1d (k=4) + SiLU, reading u = xz[:, :DI]
// ---------------------------------------------------------------------------
__global__ void dwconv_silu_k(const float* __restrict__ xz, const float* __restrict__ w,
                              const float* __restrict__ bias, float* __restrict__ u) {
    int idx = blockIdx.x*256 + threadIdx.x;     // LL*DI per batch
    int b = blockIdx.y;
    int d = idx % DI;
    int l = idx / DI;
    const float* src = xz + (size_t)b*LL*(2*DI) + d;
    float acc = bias[d];
    #pragma unroll
    for (int j = 0; j < 4; ++j) {
        int ll = l - 3 + j;
        if (ll >= 0) acc += src[(size_t)ll*(2*DI)] * w[d*4 + j];
    }
    u[((size_t)b*LL + l)*DI + d] = acc * (1.f/(1.f + __expf(-acc)));
}

// ---------------------------------------------------------------------------
// selective scan: 16 state-lanes per (b,d) group, 2 groups per warp.
// Fuses  y = (scan + u*Dp) * silu(z).
// ---------------------------------------------------------------------------
__global__ __launch_bounds__(256)
void scan_k(const float* __restrict__ dl, const float* __restrict__ ua,
            const float* __restrict__ xdb, const float* __restrict__ xz,
            const float* __restrict__ alog, const float* __restrict__ Dpv,
            float* __restrict__ yo)
{
    int g = blockIdx.x*256 + threadIdx.x;
    int grp = g >> 4;              // (b,d) group, 0..767
    int s   = g & 15;              // state lane
    int b = grp / DI;
    int d = grp % DI;

    float Av = -__expf(alog[d*DST + s]);
    float Dv = Dpv[d];

    const float* pdl = dl  + (size_t)b*LL*DI + d;
    const float* pu  = ua  + (size_t)b*LL*DI + d;
    const float* px  = xdb + (size_t)b*LL*NXDB;
    const float* pz  = xz  + (size_t)b*LL*(2*DI) + DI + d;
    float* py        = yo  + (size_t)b*LL*DI + d;

    float h = 0.f;
    #pragma unroll 2
    for (int l = 0; l < LL; ++l) {
        float delta = pdl[(size_t)l*DI];
        float u     = pu [(size_t)l*DI];
        float Bv    = px[(size_t)l*NXDB + DTR + s];
        float Cv    = px[(size_t)l*NXDB + DTR + DST + s];
        h = __expf(delta*Av)*h + (delta*u)*Bv;
        float p = h*Cv;
        p += __shfl_xor_sync(0xffffffffu, p, 1);
        p += __shfl_xor_sync(0xffffffffu, p, 2);
        p += __shfl_xor_sync(0xffffffffu, p, 4);
        p += __shfl_xor_sync(0xffffffffu, p, 8);
        if (s == 0) {
            float z = pz[(size_t)l*(2*DI)];
            float y = (p + u*Dv) * siluf(z);
            py[(size_t)l*DI] = y;
        }
    }
}

// ---------------------------------------------------------------------------
// launch
// ---------------------------------------------------------------------------
extern "C" void kernel_launch(void* const* d_in, const int* in_sizes, int n_in,
                              void* d_out, int out_size)
{
    (void)in_sizes; (void)n_in; (void)out_size;
    const float* x    = (const float*)d_in[0];
    const float* c1w  = (const float*)d_in[1];
    const float* c1b  = (const float*)d_in[2];
    const float* c2w  = (const float*)d_in[3];
    const float* c2b  = (const float*)d_in[4];
    const float* lng  = (const float*)d_in[5];
    const float* lnb  = (const float*)d_in[6];
    const float* inpw = (const float*)d_in[7];
    const float* c1dw = (const float*)d_in[8];
    const float* c1db = (const float*)d_in[9];
    const float* xpw  = (const float*)d_in[10];
    const float* dtw  = (const float*)d_in[11];
    const float* dtb  = (const float*)d_in[12];
    const float* alog = (const float*)d_in[13];
    const float* Dpv  = (const float*)d_in[14];
    const float* outw = (const float*)d_in[15];
    float* out = (float*)d_out;

    float *w1t, *w2t, *y1, *y2, *xc, *xn, *xz, *ua, *xdb, *dl, *yy;
    float2 *part, *p1, *p2;
    cudaGetSymbolAddress((void**)&w1t,  g_w1t);
    cudaGetSymbolAddress((void**)&w2t,  g_w2t);
    cudaGetSymbolAddress((void**)&y1,   g_y1);
    cudaGetSymbolAddress((void**)&y2,   g_y2);
    cudaGetSymbolAddress((void**)&xc,   g_xc);
    cudaGetSymbolAddress((void**)&xn,   g_xn);
    cudaGetSymbolAddress((void**)&xz,   g_xz);
    cudaGetSymbolAddress((void**)&ua,   g_ua);
    cudaGetSymbolAddress((void**)&xdb,  g_xdb);
    cudaGetSymbolAddress((void**)&dl,   g_dl);
    cudaGetSymbolAddress((void**)&yy,   g_yy);
    cudaGetSymbolAddress((void**)&part, g_part);
    cudaGetSymbolAddress((void**)&p1,   g_p1);
    cudaGetSymbolAddress((void**)&p2,   g_p2);

    const int TWB = (27*CC*CC + 255)/256;

    // conv1
    transpose_w_k<<<TWB, 256>>>(c1w, w1t);
    conv3d_k<false><<<dim3(HH, TT, BSZ), 256>>>(x, w1t, c1b, nullptr, y1);
    stat_partial_k<<<dim3(128, BSZ), 192>>>(y1, part);
    stat_final_k<<<1, BSZ*CC>>>(part, p1);

    // conv2 with fused leaky(instnorm()) on input, then instnorm2 + residual
    transpose_w_k<<<TWB, 256>>>(c2w, w2t);
    conv3d_k<true><<<dim3(HH, TT, BSZ), 256>>>(y1, w2t, c2b, p1, y2);
    stat_partial_k<<<dim3(128, BSZ), 192>>>(y2, part);
    stat_final_k<<<1, BSZ*CC>>>(part, p2);
    apply_nr_k<<<(int)(((size_t)BL*CC + 255)/256), 256>>>(y2, x, p2, xc);

    // layernorm over gathered tokens
    ln_k<<<dim3(LL/256, BSZ), 256>>>(xc, lng, lnb, xn);

    // xz = x_norm @ in_proj_w^T        (M=32768, N=768, K=192)
    gemm_k<0><<<dim3((2*DI)/64, BL/64), 256>>>(xn, CC, inpw, nullptr, xz, 2*DI, 2*DI, CC);

    // depthwise causal conv1d + silu -> u
    dwconv_silu_k<<<dim3((LL*DI)/256, BSZ), 256>>>(xz, c1dw, c1db, ua);

    // xdb = u @ x_proj_w^T             (N=44, K=384)
    gemm_k<0><<<dim3(1, BL/64), 256>>>(ua, DI, xpw, nullptr, xdb, NXDB, NXDB, DI);

    // delta = softplus(dt @ dt_proj_w^T + dt_b)   (A = xdb[:, :12], lda=44, K=12)
    gemm_k<1><<<dim3(DI/64, BL/64), 256>>>(xdb, NXDB, dtw, dtb, dl, DI, DI, DTR);

    // selective scan (fused +u*Dp and *silu(z))
    scan_k<<<(BSZ*DI*DST)/256, 256>>>(dl, ua, xdb, xz, alog, Dpv, yy);

    // out = y @ out_proj_w^T -> d_out  (N=192, K=384)
    gemm_k<0><<<dim3(CC/64, BL/64), 256>>>(yy, DI, outw, nullptr, out, CC, CC, DI);
}

// round 8
// speedup vs baseline: 3.7088x; 3.7088x over previous
#include <cuda_runtime.h>
#include <math.h>

#define BSZ 2
#define TT 16
#define HH 32
#define WW 32
#define CC 192
#define LL 16384            // TT*HH*WW
#define DI 384
#define DTR 12
#define DST 16
#define NXDB 44             // DTR + 2*DST
#define BL (BSZ*LL)         // 32768
#define EPSV 1e-5f

// scan chunking
#define NC 64               // chunks per sequence
#define CL 256              // chunk length (NC*CL == LL)
#define NGRP (BSZ*DI)       // 768 (b,d) groups

// ---------------------------------------------------------------------------
// scratch (device globals; no allocation allowed)
// ---------------------------------------------------------------------------
__device__ float  g_w1t[27*CC*CC];
__device__ float  g_w2t[27*CC*CC];
__device__ float  g_y1 [(size_t)BL*CC];
__device__ float  g_y2 [(size_t)BL*CC];
__device__ float  g_xc [(size_t)BL*CC];
__device__ float  g_xn [(size_t)BL*CC];
__device__ float  g_xz [(size_t)BL*2*DI];
__device__ float  g_ua [(size_t)BL*DI];
__device__ float  g_xdb[(size_t)BL*NXDB];
__device__ float  g_dl [(size_t)BL*DI];
__device__ float  g_yy [(size_t)BL*DI];
__device__ float2 g_part[BSZ*128*CC];
__device__ float2 g_p1[BSZ*CC];
__device__ float2 g_p2[BSZ*CC];
__device__ float2 g_chk[(size_t)NGRP*NC*DST];   // per-chunk (prodA, scan0)
__device__ float  g_h0 [(size_t)NGRP*NC*DST];   // per-chunk initial state

__device__ __forceinline__ float softplusf(float v) {
    return v > 20.f ? v : log1pf(__expf(v));
}
__device__ __forceinline__ float siluf(float v) {
    return v / (1.f + __expf(-v));
}

// ---------------------------------------------------------------------------
// weight transpose: (co,ci,dt,dh,dw) -> [tap][ci][co], tap = (dt*3+dh)*3+dw
// ---------------------------------------------------------------------------
__global__ void transpose_w_k(const float* __restrict__ w, float* __restrict__ wt) {
    int idx = blockIdx.x * 256 + threadIdx.x;
    if (idx >= 27*CC*CC) return;
    int co  = idx % CC;
    int ci  = (idx / CC) % CC;
    int tap = idx / (CC*CC);
    wt[idx] = w[((size_t)co*CC + ci)*27 + tap];
}

// ---------------------------------------------------------------------------
// 3D conv (channel-last). One block per (b,t,h): 32 w x 192 co outputs.
// NORM_IN: input element -> leaky(instnorm(v)) using nprm (mean,rstd) per (b,c).
// ---------------------------------------------------------------------------
template<bool NORM_IN>
__global__ __launch_bounds__(256)
void conv3d_k(const float* __restrict__ in, const float* __restrict__ wT,
              const float* __restrict__ bias, const float2* __restrict__ nprm,
              float* __restrict__ out)
{
    __shared__ float in_s[34*CC];   // w = -1..32 (index = w+1), per (dt,dh)
    __shared__ float w_s[24*CC];    // 24 ci x 192 co chunk

    const int tid = threadIdx.x;
    const int h = blockIdx.x, t = blockIdx.y, b = blockIdx.z;
    const int wg = tid >> 5;        // 0..7  -> w = wg*4+iw
    const int cg = tid & 31;        // 0..31 -> co = cg + 32*j

    float acc[4][6];
    #pragma unroll
    for (int i = 0; i < 4; ++i)
        #pragma unroll
        for (int j = 0; j < 6; ++j) acc[i][j] = 0.f;

    for (int dt = 0; dt < 3; ++dt) {
        int ti = t + dt - 1;
        if ((unsigned)ti >= TT) continue;
        for (int dh = 0; dh < 3; ++dh) {
            int hi = h + dh - 1;
            if ((unsigned)hi >= HH) continue;      // block-uniform
            __syncthreads();
            {
                const float* src = in + (((size_t)(b*TT + ti)*HH + hi)*WW)*CC;
                for (int i = tid; i < 34*CC; i += 256) {
                    int pos = i / CC, c = i - pos*CC;
                    int wi = pos - 1;
                    float v = 0.f;
                    if ((unsigned)wi < WW) {
                        v = src[(size_t)wi*CC + c];
                        if (NORM_IN) {
                            float2 p = nprm[b*CC + c];
                            v = (v - p.x) * p.y;
                            v = v >= 0.f ? v : 0.01f*v;
                        }
                    }
                    in_s[i] = v;
                }
            }
            for (int dw = 0; dw < 3; ++dw) {
                const int tap = (dt*3 + dh)*3 + dw;
                const float* wt = wT + (size_t)tap*CC*CC;
                for (int c0 = 0; c0 < CC; c0 += 24) {
                    __syncthreads();
                    for (int i = tid; i < 24*CC; i += 256)
                        w_s[i] = wt[(size_t)c0*CC + i];
                    __syncthreads();
                    #pragma unroll 6
                    for (int ci = 0; ci < 24; ++ci) {
                        float wv[6];
                        #pragma unroll
                        for (int j = 0; j < 6; ++j) wv[j] = w_s[ci*CC + cg + 32*j];
                        #pragma unroll
                        for (int iw = 0; iw < 4; ++iw) {
                            float a = in_s[(wg*4 + iw + dw)*CC + c0 + ci];
                            #pragma unroll
                            for (int j = 0; j < 6; ++j) acc[iw][j] += a * wv[j];
                        }
                    }
                }
            }
        }
    }

    float* dst = out + (((size_t)(b*TT + t)*HH + h)*WW)*CC;
    #pragma unroll
    for (int iw = 0; iw < 4; ++iw) {
        int w = wg*4 + iw;
        #pragma unroll
        for (int j = 0; j < 6; ++j) {
            int co = cg + 32*j;
            dst[(size_t)w*CC + co] = acc[iw][j] + bias[co];
        }
    }
}

// ---------------------------------------------------------------------------
// instance-norm statistics: partial sums then finalize to (mean, rstd)
// ---------------------------------------------------------------------------
__global__ void stat_partial_k(const float* __restrict__ y, float2* __restrict__ part) {
    int b = blockIdx.y, ch = blockIdx.x, c = threadIdx.x;   // 192 threads
    const float* src = y + ((size_t)b*LL + (size_t)ch*128)*CC + c;
    float s = 0.f, q = 0.f;
    for (int l = 0; l < 128; ++l) {
        float v = src[(size_t)l*CC];
        s += v; q += v*v;
    }
    part[((size_t)b*128 + ch)*CC + c] = make_float2(s, q);
}

__global__ void stat_final_k(const float2* __restrict__ part, float2* __restrict__ p) {
    int idx = threadIdx.x;            // 384 = BSZ*CC
    int b = idx / CC, c = idx % CC;
    float s = 0.f, q = 0.f;
    for (int k = 0; k < 128; ++k) {
        float2 v = part[((size_t)b*128 + k)*CC + c];
        s += v.x; q += v.y;
    }
    float mu  = s * (1.f/(float)LL);
    float var = q * (1.f/(float)LL) - mu*mu;
    p[idx] = make_float2(mu, rsqrtf(fmaxf(var, 0.f) + EPSV));
}

// ---------------------------------------------------------------------------
// xc = instnorm2(y2) + residual(x)
// ---------------------------------------------------------------------------
__global__ void apply_nr_k(const float* __restrict__ y2, const float* __restrict__ x,
                           const float2* __restrict__ p, float* __restrict__ xc) {
    size_t i = (size_t)blockIdx.x*256 + threadIdx.x;
    if (i >= (size_t)BL*CC) return;
    int c = (int)(i % CC);
    int b = (int)(i / ((size_t)LL*CC));
    float2 pr = p[b*CC + c];
    xc[i] = (y2[i] - pr.x)*pr.y + x[i];
}

// ---------------------------------------------------------------------------
// LayerNorm over the "reshape" tokens: token (b,l) gathers xc_flat[b][d*LL + l]
// for d=0..191, normalizes over d, writes row-major x_norm[(b*LL+l)*192 + d].
// ---------------------------------------------------------------------------
__global__ __launch_bounds__(256)
void ln_k(const float* __restrict__ xc, const float* __restrict__ g,
          const float* __restrict__ be, float* __restrict__ xn) {
    int l = blockIdx.x*256 + threadIdx.x;
    int b = blockIdx.y;
    const float* base = xc + (size_t)b*LL*CC;
    float s = 0.f, q = 0.f;
    for (int d = 0; d < CC; ++d) {
        float v = base[(size_t)d*LL + l];
        s += v; q += v*v;
    }
    float mu = s * (1.f/(float)CC);
    float rs = rsqrtf(fmaxf(q*(1.f/(float)CC) - mu*mu, 0.f) + EPSV);
    float* o = xn + ((size_t)b*LL + l)*CC;
    for (int d = 0; d < CC; ++d) {
        float v = base[(size_t)d*LL + l];
        o[d] = (v - mu)*rs*g[d] + be[d];
    }
}

// ---------------------------------------------------------------------------
// SGEMM: C[M,N] = A[M,K] @ B[N,K]^T   (B row-major [N,K])
// EPI: 0 = none, 1 = softplus(acc + bias[n])
// BM=BN=64, BK=16, 256 threads, 4x4 per thread.
// ---------------------------------------------------------------------------
template<int EPI>
__global__ __launch_bounds__(256)
void gemm_k(const float* __restrict__ A, int lda,
            const float* __restrict__ Bw, const float* __restrict__ bias,
            float* __restrict__ C, int ldc, int N, int K)
{
    __shared__ __align__(16) float As[16][68];
    __shared__ __align__(16) float Bs[16][68];

    const int tid = threadIdx.x;
    const int n0 = blockIdx.x * 64, m0 = blockIdx.y * 64;
    const int tm = tid >> 4, tn = tid & 15;
    const int lr = tid >> 2;          // 0..63 tile row
    const int lc = (tid & 3) << 2;    // 0,4,8,12 k offset

    float acc[4][4];
    #pragma unroll
    for (int i = 0; i < 4; ++i)
        #pragma unroll
        for (int j = 0; j < 4; ++j) acc[i][j] = 0.f;

    for (int k0 = 0; k0 < K; k0 += 16) {
        float4 av = make_float4(0.f,0.f,0.f,0.f);
        float4 bv = make_float4(0.f,0.f,0.f,0.f);
        if (k0 + lc < K)
            av = *(const float4*)(A + (size_t)(m0 + lr)*lda + k0 + lc);
        if ((n0 + lr) < N && (k0 + lc) < K)
            bv = *(const float4*)(Bw + (size_t)(n0 + lr)*K + k0 + lc);
        __syncthreads();
        As[lc+0][lr]=av.x; As[lc+1][lr]=av.y; As[lc+2][lr]=av.z; As[lc+3][lr]=av.w;
        Bs[lc+0][lr]=bv.x; Bs[lc+1][lr]=bv.y; Bs[lc+2][lr]=bv.z; Bs[lc+3][lr]=bv.w;
        __syncthreads();
        #pragma unroll
        for (int kk = 0; kk < 16; ++kk) {
            float4 ra = *(const float4*)&As[kk][tm*4];
            float4 rb = *(const float4*)&Bs[kk][tn*4];
            acc[0][0] += ra.x*rb.x; acc[0][1] += ra.x*rb.y; acc[0][2] += ra.x*rb.z; acc[0][3] += ra.x*rb.w;
            acc[1][0] += ra.y*rb.x; acc[1][1] += ra.y*rb.y; acc[1][2] += ra.y*rb.z; acc[1][3] += ra.y*rb.w;
            acc[2][0] += ra.z*rb.x; acc[2][1] += ra.z*rb.y; acc[2][2] += ra.z*rb.z; acc[2][3] += ra.z*rb.w;
            acc[3][0] += ra.w*rb.x; acc[3][1] += ra.w*rb.y; acc[3][2] += ra.w*rb.z; acc[3][3] += ra.w*rb.w;
        }
    }

    #pragma unroll
    for (int i = 0; i < 4; ++i) {
        int m = m0 + tm*4 + i;
        #pragma unroll
        for (int j = 0; j < 4; ++j) {
            int n = n0 + tn*4 + j;
            if (n < N) {
                float v = acc[i][j];
                if (EPI == 1) v = softplusf(v + bias[n]);
                C[(size_t)m*ldc + n] = v;
            }
        }
    }
}

// ---------------------------------------------------------------------------
// causal depthwise conv1d (k=4) + SiLU, reading u = xz[:, :DI]
// ---------------------------------------------------------------------------
__global__ void dwconv_silu_k(const float* __restrict__ xz, const float* __restrict__ w,
                              const float* __restrict__ bias, float* __restrict__ u) {
    int idx = blockIdx.x*256 + threadIdx.x;     // LL*DI per batch
    int b = blockIdx.y;
    int d = idx % DI;
    int l = idx / DI;
    const float* src = xz + (size_t)b*LL*(2*DI) + d;
    float acc = bias[d];
    #pragma unroll
    for (int j = 0; j < 4; ++j) {
        int ll = l - 3 + j;
        if (ll >= 0) acc += src[(size_t)ll*(2*DI)] * w[d*4 + j];
    }
    u[((size_t)b*LL + l)*DI + d] = acc * (1.f/(1.f + __expf(-acc)));
}

// ---------------------------------------------------------------------------
// chunked parallel selective scan.
// Thread id g = ((grp*NC + chunk)*16 + s), grp = b*DI + d, s = state lane.
//
// pass1: per chunk compute (Pa = prod a_l, Sq = scan result from h=0).
// combine: sequential over the NC=64 chunks per (grp,s); writes initial h0.
// pass2: replay each chunk from h0, fusing y = (h.C + u*Dp) * silu(z).
// ---------------------------------------------------------------------------
__global__ __launch_bounds__(256)
void scan_p1_k(const float* __restrict__ dl, const float* __restrict__ ua,
               const float* __restrict__ xdb, const float* __restrict__ alog,
               float2* __restrict__ chk)
{
    int g = blockIdx.x*256 + threadIdx.x;       // NGRP*NC*16 threads
    int s = g & 15;
    int gc = g >> 4;
    int chunk = gc & (NC - 1);
    int grp = gc >> 6;                          // NC == 64
    int b = grp / DI;
    int d = grp - b*DI;

    float Av = -__expf(alog[d*DST + s]);
    const int l0 = chunk * CL;
    const float* pdl = dl  + (size_t)b*LL*DI + (size_t)l0*DI + d;
    const float* pu  = ua  + (size_t)b*LL*DI + (size_t)l0*DI + d;
    const float* px  = xdb + (size_t)b*LL*NXDB + (size_t)l0*NXDB;

    float Pa = 1.f, h = 0.f;
    #pragma unroll 4
    for (int l = 0; l < CL; ++l) {
        float delta = pdl[(size_t)l*DI];
        float u     = pu [(size_t)l*DI];
        float Bv    = px[(size_t)l*NXDB + DTR + s];
        float a = __expf(delta*Av);
        Pa *= a;
        h = a*h + (delta*u)*Bv;
    }
    chk[g] = make_float2(Pa, h);
}

__global__ __launch_bounds__(256)
void scan_comb_k(const float2* __restrict__ chk, float* __restrict__ h0)
{
    int gi = blockIdx.x*256 + threadIdx.x;      // NGRP*16 threads
    if (gi >= NGRP*DST) return;
    int s = gi & 15;
    int grp = gi >> 4;
    float h = 0.f;
    #pragma unroll 8
    for (int c = 0; c < NC; ++c) {
        size_t idx = (((size_t)grp*NC + c) << 4) + s;
        float2 v = chk[idx];
        h0[idx] = h;
        h = v.x*h + v.y;
    }
}

__global__ __launch_bounds__(256)
void scan_p2_k(const float* __restrict__ dl, const float* __restrict__ ua,
               const float* __restrict__ xdb, const float* __restrict__ xz,
               const float* __restrict__ alog, const float* __restrict__ Dpv,
               const float* __restrict__ h0, float* __restrict__ yo)
{
    int g = blockIdx.x*256 + threadIdx.x;
    int s = g & 15;
    int gc = g >> 4;
    int chunk = gc & (NC - 1);
    int grp = gc >> 6;
    int b = grp / DI;
    int d = grp - b*DI;

    float Av = -__expf(alog[d*DST + s]);
    float Dv = Dpv[d];
    const int l0 = chunk * CL;
    const float* pdl = dl  + (size_t)b*LL*DI + (size_t)l0*DI + d;
    const float* pu  = ua  + (size_t)b*LL*DI + (size_t)l0*DI + d;
    const float* px  = xdb + (size_t)b*LL*NXDB + (size_t)l0*NXDB;
    const float* pz  = xz  + (size_t)b*LL*(2*DI) + (size_t)l0*(2*DI) + DI + d;
    float* py        = yo  + (size_t)b*LL*DI + (size_t)l0*DI + d;

    float h = h0[g];
    #pragma unroll 2
    for (int l = 0; l < CL; ++l) {
        float delta = pdl[(size_t)l*DI];
        float u     = pu [(size_t)l*DI];
        float Bv    = px[(size_t)l*NXDB + DTR + s];
        float Cv    = px[(size_t)l*NXDB + DTR + DST + s];
        h = __expf(delta*Av)*h + (delta*u)*Bv;
        float p = h*Cv;
        p += __shfl_xor_sync(0xffffffffu, p, 1);
        p += __shfl_xor_sync(0xffffffffu, p, 2);
        p += __shfl_xor_sync(0xffffffffu, p, 4);
        p += __shfl_xor_sync(0xffffffffu, p, 8);
        if (s == 0) {
            float z = pz[(size_t)l*(2*DI)];
            py[(size_t)l*DI] = (p + u*Dv) * siluf(z);
        }
    }
}

// ---------------------------------------------------------------------------
// launch
// ---------------------------------------------------------------------------
extern "C" void kernel_launch(void* const* d_in, const int* in_sizes, int n_in,
                              void* d_out, int out_size)
{
    (void)in_sizes; (void)n_in; (void)out_size;
    const float* x    = (const float*)d_in[0];
    const float* c1w  = (const float*)d_in[1];
    const float* c1b  = (const float*)d_in[2];
    const float* c2w  = (const float*)d_in[3];
    const float* c2b  = (const float*)d_in[4];
    const float* lng  = (const float*)d_in[5];
    const float* lnb  = (const float*)d_in[6];
    const float* inpw = (const float*)d_in[7];
    const float* c1dw = (const float*)d_in[8];
    const float* c1db = (const float*)d_in[9];
    const float* xpw  = (const float*)d_in[10];
    const float* dtw  = (const float*)d_in[11];
    const float* dtb  = (const float*)d_in[12];
    const float* alog = (const float*)d_in[13];
    const float* Dpv  = (const float*)d_in[14];
    const float* outw = (const float*)d_in[15];
    float* out = (float*)d_out;

    float *w1t, *w2t, *y1, *y2, *xc, *xn, *xz, *ua, *xdb, *dl, *yy, *h0;
    float2 *part, *p1, *p2, *chk;
    cudaGetSymbolAddress((void**)&w1t,  g_w1t);
    cudaGetSymbolAddress((void**)&w2t,  g_w2t);
    cudaGetSymbolAddress((void**)&y1,   g_y1);
    cudaGetSymbolAddress((void**)&y2,   g_y2);
    cudaGetSymbolAddress((void**)&xc,   g_xc);
    cudaGetSymbolAddress((void**)&xn,   g_xn);
    cudaGetSymbolAddress((void**)&xz,   g_xz);
    cudaGetSymbolAddress((void**)&ua,   g_ua);
    cudaGetSymbolAddress((void**)&xdb,  g_xdb);
    cudaGetSymbolAddress((void**)&dl,   g_dl);
    cudaGetSymbolAddress((void**)&yy,   g_yy);
    cudaGetSymbolAddress((void**)&part, g_part);
    cudaGetSymbolAddress((void**)&p1,   g_p1);
    cudaGetSymbolAddress((void**)&p2,   g_p2);
    cudaGetSymbolAddress((void**)&chk,  g_chk);
    cudaGetSymbolAddress((void**)&h0,   g_h0);

    const int TWB = (27*CC*CC + 255)/256;

    // conv1
    transpose_w_k<<<TWB, 256>>>(c1w, w1t);
    conv3d_k<false><<<dim3(HH, TT, BSZ), 256>>>(x, w1t, c1b, nullptr, y1);
    stat_partial_k<<<dim3(128, BSZ), 192>>>(y1, part);
    stat_final_k<<<1, BSZ*CC>>>(part, p1);

    // conv2 with fused leaky(instnorm()) on input, then instnorm2 + residual
    transpose_w_k<<<TWB, 256>>>(c2w, w2t);
    conv3d_k<true><<<dim3(HH, TT, BSZ), 256>>>(y1, w2t, c2b, p1, y2);
    stat_partial_k<<<dim3(128, BSZ), 192>>>(y2, part);
    stat_final_k<<<1, BSZ*CC>>>(part, p2);
    apply_nr_k<<<(int)(((size_t)BL*CC + 255)/256), 256>>>(y2, x, p2, xc);

    // layernorm over gathered tokens
    ln_k<<<dim3(LL/256, BSZ), 256>>>(xc, lng, lnb, xn);

    // xz = x_norm @ in_proj_w^T        (M=32768, N=768, K=192)
    gemm_k<0><<<dim3((2*DI)/64, BL/64), 256>>>(xn, CC, inpw, nullptr, xz, 2*DI, 2*DI, CC);

    // depthwise causal conv1d + silu -> u
    dwconv_silu_k<<<dim3((LL*DI)/256, BSZ), 256>>>(xz, c1dw, c1db, ua);

    // xdb = u @ x_proj_w^T             (N=44, K=384)
    gemm_k<0><<<dim3(1, BL/64), 256>>>(ua, DI, xpw, nullptr, xdb, NXDB, NXDB, DI);

    // delta = softplus(dt @ dt_proj_w^T + dt_b)
    gemm_k<1><<<dim3(DI/64, BL/64), 256>>>(xdb, NXDB, dtw, dtb, dl, DI, DI, DTR);

    // chunked parallel selective scan (fused +u*Dp and *silu(z))
    scan_p1_k  <<<(NGRP*NC*DST)/256, 256>>>(dl, ua, xdb, alog, chk);
    scan_comb_k<<<(NGRP*DST + 255)/256, 256>>>(chk, h0);
    scan_p2_k  <<<(NGRP*NC*DST)/256, 256>>>(dl, ua, xdb, xz, alog, Dpv, h0, yy);

    // out = y @ out_proj_w^T -> d_out  (N=192, K=384)
    gemm_k<0><<<dim3(CC/64, BL/64), 256>>>(yy, DI, outw, nullptr, out, CC, CC, DI);
}

// round 10
// speedup vs baseline: 7.3584x; 1.9841x over previous
#include <cuda_runtime.h>
#include <math.h>

#define BSZ 2
#define TT 16
#define HH 32
#define WW 32
#define CC 192
#define LL 16384            // TT*HH*WW
#define DI 384
#define DTR 12
#define DST 16
#define NXDB 44             // DTR + 2*DST
#define BL (BSZ*LL)         // 32768
#define EPSV 1e-5f

// scan chunking
#define NC 64
#define CL 256
#define NGRP (BSZ*DI)

// conv mma smem geometry
#define IN_PITCH 196        // 196 % 32 == 4  -> conflict-free A frags
#define W_PITCH  200        // 200 % 32 == 8  -> conflict-free B frags
#define IN4_FLOATS (4*34*IN_PITCH)          // 26656
#define WS_FLOATS  (3*32*W_PITCH)           // 19200
#define SMEM_CONV ((IN4_FLOATS + WS_FLOATS)*4)   // 183424 bytes

// ---------------------------------------------------------------------------
// scratch (device globals; no allocation allowed)
// ---------------------------------------------------------------------------
__device__ float  g_w1t[27*CC*CC];
__device__ float  g_w2t[27*CC*CC];
__device__ float  g_y1 [(size_t)BL*CC];
__device__ float  g_y2 [(size_t)BL*CC];
__device__ float  g_xc [(size_t)BL*CC];
__device__ float  g_xn [(size_t)BL*CC];
__device__ float  g_xz [(size_t)BL*2*DI];
__device__ float  g_ua [(size_t)BL*DI];
__device__ float  g_xdb[(size_t)BL*NXDB];
__device__ float  g_dl [(size_t)BL*DI];
__device__ float  g_yy [(size_t)BL*DI];
__device__ float2 g_part[BSZ*128*CC];
__device__ float2 g_p1[BSZ*CC];
__device__ float2 g_p2[BSZ*CC];
__device__ float2 g_chk[(size_t)NGRP*NC*DST];
__device__ float  g_h0 [(size_t)NGRP*NC*DST];

__device__ __forceinline__ float softplusf(float v) {
    return v > 20.f ? v : log1pf(__expf(v));
}
__device__ __forceinline__ float siluf(float v) {
    return v / (1.f + __expf(-v));
}
__device__ __forceinline__ float f2tf32(float v) {
    unsigned u;
    asm("cvt.rna.tf32.f32 %0, %1;" : "=r"(u) : "f"(v));
    return __uint_as_float(u);
}
__device__ __forceinline__ void mma_tf32(float* d,
    unsigned a0, unsigned a1, unsigned a2, unsigned a3,
    unsigned b0, unsigned b1)
{
    asm volatile("mma.sync.aligned.m16n8k8.row.col.f32.tf32.tf32.f32 "
        "{%0,%1,%2,%3}, {%4,%5,%6,%7}, {%8,%9}, {%0,%1,%2,%3};"
        : "+f"(d[0]), "+f"(d[1]), "+f"(d[2]), "+f"(d[3])
        : "r"(a0), "r"(a1), "r"(a2), "r"(a3), "r"(b0), "r"(b1));
}

// ---------------------------------------------------------------------------
// weight transpose + tf32 round: (co,ci,tap) -> [tap][ci][co]
// ---------------------------------------------------------------------------
__global__ void transpose_w_k(const float* __restrict__ w, float* __restrict__ wt) {
    int idx = blockIdx.x * 256 + threadIdx.x;
    if (idx >= 27*CC*CC) return;
    int co  = idx % CC;
    int ci  = (idx / CC) % CC;
    int tap = idx / (CC*CC);
    wt[idx] = f2tf32(w[((size_t)co*CC + ci)*27 + tap]);
}

__global__ void dummy_k(float* p) { if (threadIdx.x == 0) p[0] = 0.f; }

// ---------------------------------------------------------------------------
// 3D conv via tf32 mma.sync (implicit GEMM).
// Block: (b, t, h pair). M=64 (2 h-rows x 32 w), N=192 co, K=27*192.
// 512 threads = 16 warps: warp_m 0..3 (16 M rows), warp_n 0..3 (48 co).
// in4 smem: 4 input h-rows x 34 w-pos x 192 ci (pitch 196).
// ws  smem: 3 dw x 32 ci x 192 co (pitch 200).
// ---------------------------------------------------------------------------
template<bool NORM_IN>
__global__ __launch_bounds__(512)
void conv_mma_k(const float* __restrict__ in, const float* __restrict__ wT,
                const float* __restrict__ bias, const float2* __restrict__ nprm,
                float* __restrict__ out)
{
    extern __shared__ float sm[];
    float* in4 = sm;
    float* ws  = sm + IN4_FLOATS;
    const unsigned* in4u = (const unsigned*)in4;
    const unsigned* wsu  = (const unsigned*)ws;

    const int tid  = threadIdx.x;
    const int lane = tid & 31, wid = tid >> 5;
    const int h0 = blockIdx.x*2, t = blockIdx.y, b = blockIdx.z;
    const int warp_m = wid >> 2;        // 0..3
    const int warp_n = wid & 3;         // 0..3
    const int rr     = warp_m >> 1;     // output h sub-row (0/1)
    const int wbase  = (warp_m & 1) * 16;
    const int n0     = warp_n * 48;

    float acc[6][4];
    #pragma unroll
    for (int j = 0; j < 6; ++j)
        #pragma unroll
        for (int i = 0; i < 4; ++i) acc[j][i] = 0.f;

    for (int dt = 0; dt < 3; ++dt) {
        int ti = t + dt - 1;
        if ((unsigned)ti >= TT) continue;          // block-uniform
        __syncthreads();
        // stage 4 input h-rows (h0-1 .. h0+2), zero-padded, tf32-rounded
        const float* inb = in + ((size_t)(b*TT + ti)*HH) * (size_t)WW * CC;
        for (int i = tid; i < 4*34*192; i += 512) {
            int c    = i % 192;
            int rest = i / 192;
            int pos  = rest % 34;
            int rh   = rest / 34;
            int hb = h0 - 1 + rh;
            int wi = pos - 1;
            float v = 0.f;
            if ((unsigned)hb < HH && (unsigned)wi < WW) {
                v = inb[((size_t)hb*WW + wi)*CC + c];
                if (NORM_IN) {
                    float2 p = nprm[b*CC + c];
                    v = (v - p.x) * p.y;
                    v = v >= 0.f ? v : 0.01f*v;
                }
            }
            in4[(rh*34 + pos)*IN_PITCH + c] = f2tf32(v);
        }
        __syncthreads();

        for (int dh = 0; dh < 3; ++dh) {
            const int rowh = rr + dh;              // input h row index (0..3)
            for (int ci0 = 0; ci0 < 192; ci0 += 32) {
                __syncthreads();
                // stage weights: 3 dw x 32 ci x 192 co (already tf32)
                for (int v4 = tid; v4 < 3*32*48; v4 += 512) {
                    int co4  = v4 % 48;
                    int rest = v4 / 48;
                    int ci   = rest % 32;
                    int dw   = rest / 32;
                    int tap = (dt*3 + dh)*3 + dw;
                    float4 wv = *(const float4*)(wT + ((size_t)tap*CC + ci0 + ci)*CC + co4*4);
                    *(float4*)(ws + (dw*32 + ci)*W_PITCH + co4*4) = wv;
                }
                __syncthreads();
                #pragma unroll
                for (int dw = 0; dw < 3; ++dw) {
                    #pragma unroll
                    for (int kk = 0; kk < 4; ++kk) {
                        int abase = (rowh*34 + wbase + (lane>>2) + dw)*IN_PITCH
                                    + ci0 + kk*8 + (lane&3);
                        unsigned a0 = in4u[abase];
                        unsigned a1 = in4u[abase + 8*IN_PITCH];
                        unsigned a2 = in4u[abase + 4];
                        unsigned a3 = in4u[abase + 8*IN_PITCH + 4];
                        int bbase = (dw*32 + kk*8 + (lane&3))*W_PITCH + n0 + (lane>>2);
                        #pragma unroll
                        for (int j = 0; j < 6; ++j) {
                            unsigned b0 = wsu[bbase + j*8];
                            unsigned b1 = wsu[bbase + 4*W_PITCH + j*8];
                            mma_tf32(acc[j], a0, a1, a2, a3, b0, b1);
                        }
                    }
                }
            }
        }
    }

    // epilogue: + bias
    const int h  = h0 + rr;
    const int w0 = wbase + (lane>>2);
    float* dst = out + (((size_t)(b*TT + t)*HH + h)*WW)*CC;
    #pragma unroll
    for (int j = 0; j < 6; ++j) {
        int co = n0 + j*8 + 2*(lane&3);
        float bx = bias[co], by = bias[co+1];
        *(float2*)(dst + (size_t)w0*CC + co)
            = make_float2(acc[j][0] + bx, acc[j][1] + by);
        *(float2*)(dst + (size_t)(w0+8)*CC + co)
            = make_float2(acc[j][2] + bx, acc[j][3] + by);
    }
}

// ---------------------------------------------------------------------------
// tf32 mma GEMM: C[M,N] = A[M,K] @ B[N,K]^T.  BM=128, BN=64, KT=32.
// 256 threads = 8 warps: warp_m 0..3 (32 M), warp_n 0..1 (32 N).
// Requires M%128==0, N%64==0, K%32==0.
// ---------------------------------------------------------------------------
__global__ __launch_bounds__(256)
void gemm_tf32_k(const float* __restrict__ A, int lda,
                 const float* __restrict__ Bw,
                 float* __restrict__ C, int ldc, int K)
{
    __shared__ float As[128*36];
    __shared__ float Bs[64*36];
    const unsigned* Asu = (const unsigned*)As;
    const unsigned* Bsu = (const unsigned*)Bs;

    const int tid = threadIdx.x, lane = tid & 31, wid = tid >> 5;
    const int n0 = blockIdx.x*64, m0 = blockIdx.y*128;
    const int warp_m = wid >> 1, warp_n = wid & 1;

    float acc[2][4][4];
    #pragma unroll
    for (int im = 0; im < 2; ++im)
        #pragma unroll
        for (int in = 0; in < 4; ++in)
            #pragma unroll
            for (int i = 0; i < 4; ++i) acc[im][in][i] = 0.f;

    for (int k0 = 0; k0 < K; k0 += 32) {
        __syncthreads();
        #pragma unroll
        for (int it = 0; it < 4; ++it) {
            int row = it*32 + (tid>>3);
            int kc  = (tid&7)*4;
            float4 v = *(const float4*)(A + (size_t)(m0+row)*lda + k0 + kc);
            v.x = f2tf32(v.x); v.y = f2tf32(v.y); v.z = f2tf32(v.z); v.w = f2tf32(v.w);
            *(float4*)(As + row*36 + kc) = v;
        }
        #pragma unroll
        for (int it = 0; it < 2; ++it) {
            int row = it*32 + (tid>>3);
            int kc  = (tid&7)*4;
            float4 v = *(const float4*)(Bw + (size_t)(n0+row)*K + k0 + kc);
            v.x = f2tf32(v.x); v.y = f2tf32(v.y); v.z = f2tf32(v.z); v.w = f2tf32(v.w);
            *(float4*)(Bs + row*36 + kc) = v;
        }
        __syncthreads();
        #pragma unroll
        for (int kk = 0; kk < 4; ++kk) {
            unsigned a[2][4];
            #pragma unroll
            for (int im = 0; im < 2; ++im) {
                int m = warp_m*32 + im*16 + (lane>>2);
                int base = m*36 + kk*8 + (lane&3);
                a[im][0] = Asu[base];
                a[im][1] = Asu[base + 8*36];
                a[im][2] = Asu[base + 4];
                a[im][3] = Asu[base + 8*36 + 4];
            }
            #pragma unroll
            for (int in = 0; in < 4; ++in) {
                int n = warp_n*32 + in*8 + (lane>>2);
                int bb = n*36 + kk*8 + (lane&3);
                unsigned b0 = Bsu[bb], b1 = Bsu[bb + 4];
                #pragma unroll
                for (int im = 0; im < 2; ++im)
                    mma_tf32(acc[im][in], a[im][0], a[im][1], a[im][2], a[im][3], b0, b1);
            }
        }
    }

    #pragma unroll
    for (int im = 0; im < 2; ++im) {
        int r = m0 + warp_m*32 + im*16 + (lane>>2);
        #pragma unroll
        for (int in = 0; in < 4; ++in) {
            int c = n0 + warp_n*32 + in*8 + 2*(lane&3);
            *(float2*)(C + (size_t)r*ldc + c)     = make_float2(acc[im][in][0], acc[im][in][1]);
            *(float2*)(C + (size_t)(r+8)*ldc + c) = make_float2(acc[im][in][2], acc[im][in][3]);
        }
    }
}

// ---------------------------------------------------------------------------
// instance-norm statistics
// ---------------------------------------------------------------------------
__global__ void stat_partial_k(const float* __restrict__ y, float2* __restrict__ part) {
    int b = blockIdx.y, ch = blockIdx.x, c = threadIdx.x;   // 192 threads
    const float* src = y + ((size_t)b*LL + (size_t)ch*128)*CC + c;
    float s = 0.f, q = 0.f;
    for (int l = 0; l < 128; ++l) {
        float v = src[(size_t)l*CC];
        s += v; q += v*v;
    }
    part[((size_t)b*128 + ch)*CC + c] = make_float2(s, q);
}

__global__ void stat_final_k(const float2* __restrict__ part, float2* __restrict__ p) {
    int idx = threadIdx.x;            // 384 = BSZ*CC
    int b = idx / CC, c = idx % CC;
    float s = 0.f, q = 0.f;
    for (int k = 0; k < 128; ++k) {
        float2 v = part[((size_t)b*128 + k)*CC + c];
        s += v.x; q += v.y;
    }
    float mu  = s * (1.f/(float)LL);
    float var = q * (1.f/(float)LL) - mu*mu;
    p[idx] = make_float2(mu, rsqrtf(fmaxf(var, 0.f) + EPSV));
}

// xc = instnorm2(y2) + residual(x)
__global__ void apply_nr_k(const float* __restrict__ y2, const float* __restrict__ x,
                           const float2* __restrict__ p, float* __restrict__ xc) {
    size_t i = (size_t)blockIdx.x*256 + threadIdx.x;
    if (i >= (size_t)BL*CC) return;
    int c = (int)(i % CC);
    int b = (int)(i / ((size_t)LL*CC));
    float2 pr = p[b*CC + c];
    xc[i] = (y2[i] - pr.x)*pr.y + x[i];
}

// ---------------------------------------------------------------------------
// LayerNorm over gathered tokens
// ---------------------------------------------------------------------------
__global__ __launch_bounds__(256)
void ln_k(const float* __restrict__ xc, const float* __restrict__ g,
          const float* __restrict__ be, float* __restrict__ xn) {
    int l = blockIdx.x*256 + threadIdx.x;
    int b = blockIdx.y;
    const float* base = xc + (size_t)b*LL*CC;
    float s = 0.f, q = 0.f;
    for (int d = 0; d < CC; ++d) {
        float v = base[(size_t)d*LL + l];
        s += v; q += v*v;
    }
    float mu = s * (1.f/(float)CC);
    float rs = rsqrtf(fmaxf(q*(1.f/(float)CC) - mu*mu, 0.f) + EPSV);
    float* o = xn + ((size_t)b*LL + l)*CC;
    for (int d = 0; d < CC; ++d) {
        float v = base[(size_t)d*LL + l];
        o[d] = (v - mu)*rs*g[d] + be[d];
    }
}

// ---------------------------------------------------------------------------
// fp32 SGEMM (kept for the small/odd-shaped projections)
// ---------------------------------------------------------------------------
template<int EPI>
__global__ __launch_bounds__(256)
void gemm_k(const float* __restrict__ A, int lda,
            const float* __restrict__ Bw, const float* __restrict__ bias,
            float* __restrict__ C, int ldc, int N, int K)
{
    __shared__ __align__(16) float As[16][68];
    __shared__ __align__(16) float Bs[16][68];

    const int tid = threadIdx.x;
    const int n0 = blockIdx.x * 64, m0 = blockIdx.y * 64;
    const int tm = tid >> 4, tn = tid & 15;
    const int lr = tid >> 2;
    const int lc = (tid & 3) << 2;

    float acc[4][4];
    #pragma unroll
    for (int i = 0; i < 4; ++i)
        #pragma unroll
        for (int j = 0; j < 4; ++j) acc[i][j] = 0.f;

    for (int k0 = 0; k0 < K; k0 += 16) {
        float4 av = make_float4(0.f,0.f,0.f,0.f);
        float4 bv = make_float4(0.f,0.f,0.f,0.f);
        if (k0 + lc < K)
            av = *(const float4*)(A + (size_t)(m0 + lr)*lda + k0 + lc);
        if ((n0 + lr) < N && (k0 + lc) < K)
            bv = *(const float4*)(Bw + (size_t)(n0 + lr)*K + k0 + lc);
        __syncthreads();
        As[lc+0][lr]=av.x; As[lc+1][lr]=av.y; As[lc+2][lr]=av.z; As[lc+3][lr]=av.w;
        Bs[lc+0][lr]=bv.x; Bs[lc+1][lr]=bv.y; Bs[lc+2][lr]=bv.z; Bs[lc+3][lr]=bv.w;
        __syncthreads();
        #pragma unroll
        for (int kk = 0; kk < 16; ++kk) {
            float4 ra = *(const float4*)&As[kk][tm*4];
            float4 rb = *(const float4*)&Bs[kk][tn*4];
            acc[0][0] += ra.x*rb.x; acc[0][1] += ra.x*rb.y; acc[0][2] += ra.x*rb.z; acc[0][3] += ra.x*rb.w;
            acc[1][0] += ra.y*rb.x; acc[1][1] += ra.y*rb.y; acc[1][2] += ra.y*rb.z; acc[1][3] += ra.y*rb.w;
            acc[2][0] += ra.z*rb.x; acc[2][1] += ra.z*rb.y; acc[2][2] += ra.z*rb.z; acc[2][3] += ra.z*rb.w;
            acc[3][0] += ra.w*rb.x; acc[3][1] += ra.w*rb.y; acc[3][2] += ra.w*rb.z; acc[3][3] += ra.w*rb.w;
        }
    }

    #pragma unroll
    for (int i = 0; i < 4; ++i) {
        int m = m0 + tm*4 + i;
        #pragma unroll
        for (int j = 0; j < 4; ++j) {
            int n = n0 + tn*4 + j;
            if (n < N) {
                float v = acc[i][j];
                if (EPI == 1) v = softplusf(v + bias[n]);
                C[(size_t)m*ldc + n] = v;
            }
        }
    }
}

// ---------------------------------------------------------------------------
// causal depthwise conv1d (k=4) + SiLU
// ---------------------------------------------------------------------------
__global__ void dwconv_silu_k(const float* __restrict__ xz, const float* __restrict__ w,
                              const float* __restrict__ bias, float* __restrict__ u) {
    int idx = blockIdx.x*256 + threadIdx.x;
    int b = blockIdx.y;
    int d = idx % DI;
    int l = idx / DI;
    const float* src = xz + (size_t)b*LL*(2*DI) + d;
    float acc = bias[d];
    #pragma unroll
    for (int j = 0; j < 4; ++j) {
        int ll = l - 3 + j;
        if (ll >= 0) acc += src[(size_t)ll*(2*DI)] * w[d*4 + j];
    }
    u[((size_t)b*LL + l)*DI + d] = acc * (1.f/(1.f + __expf(-acc)));
}

// ---------------------------------------------------------------------------
// chunked parallel selective scan
// ---------------------------------------------------------------------------
__global__ __launch_bounds__(256)
void scan_p1_k(const float* __restrict__ dl, const float* __restrict__ ua,
               const float* __restrict__ xdb, const float* __restrict__ alog,
               float2* __restrict__ chk)
{
    int g = blockIdx.x*256 + threadIdx.x;
    int s = g & 15;
    int gc = g >> 4;
    int chunk = gc & (NC - 1);
    int grp = gc >> 6;
    int b = grp / DI;
    int d = grp - b*DI;

    float Av = -__expf(alog[d*DST + s]);
    const int l0 = chunk * CL;
    const float* pdl = dl  + (size_t)b*LL*DI + (size_t)l0*DI + d;
    const float* pu  = ua  + (size_t)b*LL*DI + (size_t)l0*DI + d;
    const float* px  = xdb + (size_t)b*LL*NXDB + (size_t)l0*NXDB;

    float Pa = 1.f, h = 0.f;
    #pragma unroll 4
    for (int l = 0; l < CL; ++l) {
        float delta = pdl[(size_t)l*DI];
        float u     = pu [(size_t)l*DI];
        float Bv    = px[(size_t)l*NXDB + DTR + s];
        float a = __expf(delta*Av);
        Pa *= a;
        h = a*h + (delta*u)*Bv;
    }
    chk[g] = make_float2(Pa, h);
}

__global__ __launch_bounds__(256)
void scan_comb_k(const float2* __restrict__ chk, float* __restrict__ h0)
{
    int gi = blockIdx.x*256 + threadIdx.x;
    if (gi >= NGRP*DST) return;
    int s = gi & 15;
    int grp = gi >> 4;
    float h = 0.f;
    #pragma unroll 8
    for (int c = 0; c < NC; ++c) {
        size_t idx = (((size_t)grp*NC + c) << 4) + s;
        float2 v = chk[idx];
        h0[idx] = h;
        h = v.x*h + v.y;
    }
}

__global__ __launch_bounds__(256)
void scan_p2_k(const float* __restrict__ dl, const float* __restrict__ ua,
               const float* __restrict__ xdb, const float* __restrict__ xz,
               const float* __restrict__ alog, const float* __restrict__ Dpv,
               const float* __restrict__ h0, float* __restrict__ yo)
{
    int g = blockIdx.x*256 + threadIdx.x;
    int s = g & 15;
    int gc = g >> 4;
    int chunk = gc & (NC - 1);
    int grp = gc >> 6;
    int b = grp / DI;
    int d = grp - b*DI;

    float Av = -__expf(alog[d*DST + s]);
    float Dv = Dpv[d];
    const int l0 = chunk * CL;
    const float* pdl = dl  + (size_t)b*LL*DI + (size_t)l0*DI + d;
    const float* pu  = ua  + (size_t)b*LL*DI + (size_t)l0*DI + d;
    const float* px  = xdb + (size_t)b*LL*NXDB + (size_t)l0*NXDB;
    const float* pz  = xz  + (size_t)b*LL*(2*DI) + (size_t)l0*(2*DI) + DI + d;
    float* py        = yo  + (size_t)b*LL*DI + (size_t)l0*DI + d;

    float h = h0[g];
    #pragma unroll 2
    for (int l = 0; l < CL; ++l) {
        float delta = pdl[(size_t)l*DI];
        float u     = pu [(size_t)l*DI];
        float Bv    = px[(size_t)l*NXDB + DTR + s];
        float Cv    = px[(size_t)l*NXDB + DTR + DST + s];
        h = __expf(delta*Av)*h + (delta*u)*Bv;
        float p = h*Cv;
        p += __shfl_xor_sync(0xffffffffu, p, 1);
        p += __shfl_xor_sync(0xffffffffu, p, 2);
        p += __shfl_xor_sync(0xffffffffu, p, 4);
        p += __shfl_xor_sync(0xffffffffu, p, 8);
        if (s == 0) {
            float z = pz[(size_t)l*(2*DI)];
            py[(size_t)l*DI] = (p + u*Dv) * siluf(z);
        }
    }
}

// ---------------------------------------------------------------------------
// launch
// ---------------------------------------------------------------------------
extern "C" void kernel_launch(void* const* d_in, const int* in_sizes, int n_in,
                              void* d_out, int out_size)
{
    (void)in_sizes; (void)n_in; (void)out_size;
    const float* x    = (const float*)d_in[0];
    const float* c1w  = (const float*)d_in[1];
    const float* c1b  = (const float*)d_in[2];
    const float* c2w  = (const float*)d_in[3];
    const float* c2b  = (const float*)d_in[4];
    const float* lng  = (const float*)d_in[5];
    const float* lnb  = (const float*)d_in[6];
    const float* inpw = (const float*)d_in[7];
    const float* c1dw = (const float*)d_in[8];
    const float* c1db = (const float*)d_in[9];
    const float* xpw  = (const float*)d_in[10];
    const float* dtw  = (const float*)d_in[11];
    const float* dtb  = (const float*)d_in[12];
    const float* alog = (const float*)d_in[13];
    const float* Dpv  = (const float*)d_in[14];
    const float* outw = (const float*)d_in[15];
    float* out = (float*)d_out;

    float *w1t, *w2t, *y1, *y2, *xc, *xn, *xz, *ua, *xdb, *dl, *yy, *h0;
    float2 *part, *p1, *p2, *chk;
    cudaGetSymbolAddress((void**)&w1t,  g_w1t);
    cudaGetSymbolAddress((void**)&w2t,  g_w2t);
    cudaGetSymbolAddress((void**)&y1,   g_y1);
    cudaGetSymbolAddress((void**)&y2,   g_y2);
    cudaGetSymbolAddress((void**)&xc,   g_xc);
    cudaGetSymbolAddress((void**)&xn,   g_xn);
    cudaGetSymbolAddress((void**)&xz,   g_xz);
    cudaGetSymbolAddress((void**)&ua,   g_ua);
    cudaGetSymbolAddress((void**)&xdb,  g_xdb);
    cudaGetSymbolAddress((void**)&dl,   g_dl);
    cudaGetSymbolAddress((void**)&yy,   g_yy);
    cudaGetSymbolAddress((void**)&part, g_part);
    cudaGetSymbolAddress((void**)&p1,   g_p1);
    cudaGetSymbolAddress((void**)&p2,   g_p2);
    cudaGetSymbolAddress((void**)&chk,  g_chk);
    cudaGetSymbolAddress((void**)&h0,   g_h0);

    cudaFuncSetAttribute(conv_mma_k<false>,
        cudaFuncAttributeMaxDynamicSharedMemorySize, SMEM_CONV);
    cudaFuncSetAttribute(conv_mma_k<true>,
        cudaFuncAttributeMaxDynamicSharedMemorySize, SMEM_CONV);

    const int TWB = (27*CC*CC + 255)/256;

    transpose_w_k<<<TWB, 256>>>(c1w, w1t);
    transpose_w_k<<<TWB, 256>>>(c2w, w2t);
    dummy_k<<<1, 32>>>((float*)part);

    // conv1 (tf32 mma)
    conv_mma_k<false><<<dim3(HH/2, TT, BSZ), 512, SMEM_CONV>>>(x, w1t, c1b, nullptr, y1);
    stat_partial_k<<<dim3(128, BSZ), 192>>>(y1, part);
    stat_final_k<<<1, BSZ*CC>>>(part, p1);

    // conv2 with fused leaky(instnorm()) on input
    conv_mma_k<true><<<dim3(HH/2, TT, BSZ), 512, SMEM_CONV>>>(y1, w2t, c2b, p1, y2);
    stat_partial_k<<<dim3(128, BSZ), 192>>>(y2, part);
    stat_final_k<<<1, BSZ*CC>>>(part, p2);
    apply_nr_k<<<(int)(((size_t)BL*CC + 255)/256), 256>>>(y2, x, p2, xc);

    // layernorm over gathered tokens
    ln_k<<<dim3(LL/256, BSZ), 256>>>(xc, lng, lnb, xn);

    // xz = x_norm @ in_proj_w^T   (M=32768, N=768, K=192) tf32 mma
    gemm_tf32_k<<<dim3((2*DI)/64, BL/128), 256>>>(xn, CC, inpw, xz, 2*DI, CC);

    // depthwise causal conv1d + silu -> u
    dwconv_silu_k<<<dim3((LL*DI)/256, BSZ), 256>>>(xz, c1dw, c1db, ua);

    // xdb = u @ x_proj_w^T        (N=44, K=384) fp32
    gemm_k<0><<<dim3(1, BL/64), 256>>>(ua, DI, xpw, nullptr, xdb, NXDB, NXDB, DI);

    // delta = softplus(dt @ dt_proj_w^T + dt_b) fp32
    gemm_k<1><<<dim3(DI/64, BL/64), 256>>>(xdb, NXDB, dtw, dtb, dl, DI, DI, DTR);

    // chunked parallel selective scan
    scan_p1_k  <<<(NGRP*NC*DST)/256, 256>>>(dl, ua, xdb, alog, chk);
    scan_comb_k<<<(NGRP*DST + 255)/256, 256>>>(chk, h0);
    scan_p2_k  <<<(NGRP*NC*DST)/256, 256>>>(dl, ua, xdb, xz, alog, Dpv, h0, yy);

    // out = y @ out_proj_w^T -> d_out  (N=192, K=384) tf32 mma
    gemm_tf32_k<<<dim3(CC/64, BL/128), 256>>>(yy, DI, outw, out, CC, DI);
}

// round 13
// speedup vs baseline: 10.4510x; 1.4203x over previous
#include <cuda_runtime.h>
#include <cuda_fp16.h>
#include <math.h>

#define BSZ 2
#define TT 16
#define HH 32
#define WW 32
#define CC 192
#define LL 16384            // TT*HH*WW
#define DI 384
#define DTR 12
#define DST 16
#define NXDB 44             // DTR + 2*DST
#define BL (BSZ*LL)         // 32768
#define EPSV 1e-5f

// scan chunking
#define NC 64
#define CL 256
#define NGRP (BSZ*DI)

// conv fp16 smem geometry (units = halves)
#define INP 200             // input pitch: 400B, 400%128==16 -> ldmatrix conflict-free
#define WP  40              // weight pitch: 80B = 16*5 -> conflict-free
#define IN4_H (4*34*INP)    // 27200 halves
#define WS_H  (3*CC*WP)     // 23040 halves
#define SMEM_CONVH ((IN4_H + WS_H)*2)   // 100480 bytes -> 2 CTAs/SM

// ---------------------------------------------------------------------------
// scratch (device globals; no allocation allowed)
// ---------------------------------------------------------------------------
__device__ __half g_w1h[27*CC*CC];      // [tap][co][ci]
__device__ __half g_w2h[27*CC*CC];
__device__ __half g_wih[2*DI*CC];       // in_proj  [N][K]
__device__ __half g_woh[CC*DI];         // out_proj [N][K]
__device__ float  g_y1 [(size_t)BL*CC];
__device__ float  g_y2 [(size_t)BL*CC];
__device__ float  g_xc [(size_t)BL*CC];
__device__ float  g_xn [(size_t)BL*CC];
__device__ float  g_xz [(size_t)BL*2*DI];
__device__ float  g_ua [(size_t)BL*DI];
__device__ float  g_xdb[(size_t)BL*NXDB];
__device__ float  g_dl [(size_t)BL*DI];
__device__ float  g_yy [(size_t)BL*DI];
__device__ float2 g_part[BSZ*128*CC];
__device__ float2 g_p1[BSZ*CC];
__device__ float2 g_p2[BSZ*CC];
__device__ float2 g_chk[(size_t)NGRP*NC*DST];
__device__ float  g_h0 [(size_t)NGRP*NC*DST];

__device__ __forceinline__ float softplusf(float v) {
    return v > 20.f ? v : log1pf(__expf(v));
}
__device__ __forceinline__ float siluf(float v) {
    return v / (1.f + __expf(-v));
}
__device__ __forceinline__ void ldsm4(unsigned& r0, unsigned& r1, unsigned& r2, unsigned& r3,
                                      unsigned addr) {
    asm volatile("ldmatrix.sync.aligned.m8n8.x4.shared.b16 {%0,%1,%2,%3}, [%4];"
        : "=r"(r0), "=r"(r1), "=r"(r2), "=r"(r3) : "r"(addr));
}
__device__ __forceinline__ void mma_f16(float* d,
    unsigned a0, unsigned a1, unsigned a2, unsigned a3, unsigned b0, unsigned b1)
{
    asm volatile("mma.sync.aligned.m16n8k16.row.col.f32.f16.f16.f32 "
        "{%0,%1,%2,%3}, {%4,%5,%6,%7}, {%8,%9}, {%0,%1,%2,%3};"
        : "+f"(d[0]), "+f"(d[1]), "+f"(d[2]), "+f"(d[3])
        : "r"(a0), "r"(a1), "r"(a2), "r"(a3), "r"(b0), "r"(b1));
}

// ---------------------------------------------------------------------------
// weight converts
// ---------------------------------------------------------------------------
// (co,ci,tap) fp32 -> [tap][co][ci] half
__global__ void conv_w_half_k(const float* __restrict__ w, __half* __restrict__ wh) {
    int idx = blockIdx.x * 256 + threadIdx.x;
    if (idx >= 27*CC*CC) return;
    int ci  = idx % CC;
    int co  = (idx / CC) % CC;
    int tap = idx / (CC*CC);
    wh[idx] = __float2half_rn(w[((size_t)co*CC + ci)*27 + tap]);
}
__global__ void proj_w_half_k(const float* __restrict__ w, __half* __restrict__ wh, int n) {
    int i = blockIdx.x * 256 + threadIdx.x;
    if (i < n) wh[i] = __float2half_rn(w[i]);
}
__global__ void dummy_k(float* p) { if (threadIdx.x == 0) p[0] = 0.f; }

// ---------------------------------------------------------------------------
// 3D conv via fp16 mma.m16n8k16 + ldmatrix (implicit GEMM).
// Block: (b, t, h pair). M=64 (2 h-rows x 32 w), N=192 co, K=27*192.
// 512 threads = 16 warps: warp_m 0..3 (16 w), warp_n 0..3 (48 co).
// in4 smem: 4 input h-rows x 34 w-pos x 192 ci (half, pitch INP).
// ws  smem: 3 dw x 192 co x 32 ci chunk (half, pitch WP), rows = co (n-major).
// ---------------------------------------------------------------------------
template<bool NORM_IN>
__global__ __launch_bounds__(512, 2)
void conv_f16_k(const float* __restrict__ in, const __half* __restrict__ wH,
                const float* __restrict__ bias, const float2* __restrict__ nprm,
                float* __restrict__ out)
{
    extern __shared__ __half smh[];
    __half* in4 = smh;
    __half* ws  = smh + IN4_H;
    const unsigned in4_base = (unsigned)__cvta_generic_to_shared(in4);
    const unsigned ws_base  = (unsigned)__cvta_generic_to_shared(ws);

    const int tid  = threadIdx.x;
    const int lane = tid & 31, wid = tid >> 5;
    const int h0 = blockIdx.x*2, t = blockIdx.y, b = blockIdx.z;
    const int warp_m = wid >> 2;
    const int warp_n = wid & 3;
    const int rr     = warp_m >> 1;
    const int wbase  = (warp_m & 1) * 16;
    const int n0     = warp_n * 48;

    // per-thread ldmatrix lane offsets
    const int a_row = wbase + (lane & 15);
    const int a_kof = (lane >> 4) * 8;
    const int b_n   = n0 + (lane >> 4) * 8 + (lane & 7);
    const int b_kof = ((lane >> 3) & 1) * 8;

    float acc[6][4];
    #pragma unroll
    for (int j = 0; j < 6; ++j)
        #pragma unroll
        for (int i = 0; i < 4; ++i) acc[j][i] = 0.f;

    for (int dt = 0; dt < 3; ++dt) {
        int ti = t + dt - 1;
        if ((unsigned)ti >= TT) continue;          // block-uniform
        __syncthreads();
        // stage 4 input h-rows (h0-1 .. h0+2), fp32 -> half, zero-padded
        const float* inb = in + ((size_t)(b*TT + ti)*HH) * (size_t)WW * CC;
        for (int v = tid; v < 4*34*48; v += 512) {
            int c4   = v % 48;
            int rest = v / 48;
            int pos  = rest % 34;
            int rh   = rest / 34;
            int hb = h0 - 1 + rh;
            int wi = pos - 1;
            int c = c4*4;
            float4 val = make_float4(0.f,0.f,0.f,0.f);
            if ((unsigned)hb < HH && (unsigned)wi < WW) {
                val = *(const float4*)(inb + ((size_t)hb*WW + wi)*CC + c);
                if (NORM_IN) {
                    float2 p0 = nprm[b*CC + c + 0];
                    float2 p1 = nprm[b*CC + c + 1];
                    float2 p2 = nprm[b*CC + c + 2];
                    float2 p3 = nprm[b*CC + c + 3];
                    val.x = (val.x - p0.x)*p0.y; val.x = val.x >= 0.f ? val.x : 0.01f*val.x;
                    val.y = (val.y - p1.x)*p1.y; val.y = val.y >= 0.f ? val.y : 0.01f*val.y;
                    val.z = (val.z - p2.x)*p2.y; val.z = val.z >= 0.f ? val.z : 0.01f*val.z;
                    val.w = (val.w - p3.x)*p3.y; val.w = val.w >= 0.f ? val.w : 0.01f*val.w;
                }
            }
            __half2* dst = (__half2*)(in4 + (rh*34 + pos)*INP + c);
            dst[0] = __floats2half2_rn(val.x, val.y);
            dst[1] = __floats2half2_rn(val.z, val.w);
        }
        __syncthreads();

        for (int dh = 0; dh < 3; ++dh) {
            const int rowh = rr + dh;
            for (int c0 = 0; c0 < CC; c0 += 32) {
                __syncthreads();
                // stage weights: 3 dw x 192 co x 32 ci, rows = co
                for (int v = tid; v < 3*CC*4; v += 512) {
                    int q    = v & 3;
                    int rest = v >> 2;
                    int co   = rest % CC;
                    int dw   = rest / CC;
                    int tap = (dt*3 + dh)*3 + dw;
                    uint4 wv = *(const uint4*)(wH + ((size_t)tap*CC + co)*CC + c0 + q*8);
                    *(uint4*)(ws + (dw*CC + co)*WP + q*8) = wv;
                }
                __syncthreads();
                #pragma unroll
                for (int dw = 0; dw < 3; ++dw) {
                    #pragma unroll
                    for (int ks = 0; ks < 2; ++ks) {
                        unsigned a0,a1,a2,a3;
                        unsigned aaddr = in4_base +
                            (((rowh*34 + a_row + dw)*INP + c0 + ks*16 + a_kof) << 1);
                        ldsm4(a0,a1,a2,a3, aaddr);
                        #pragma unroll
                        for (int jp = 0; jp < 3; ++jp) {
                            unsigned b0,b1,b2,b3;
                            unsigned baddr = ws_base +
                                (((dw*CC + b_n + jp*16)*WP + ks*16 + b_kof) << 1);
                            ldsm4(b0,b1,b2,b3, baddr);
                            mma_f16(acc[jp*2+0], a0,a1,a2,a3, b0,b1);
                            mma_f16(acc[jp*2+1], a0,a1,a2,a3, b2,b3);
                        }
                    }
                }
            }
        }
    }

    // epilogue: + bias
    const int h  = h0 + rr;
    const int w0 = wbase + (lane>>2);
    float* dst = out + (((size_t)(b*TT + t)*HH + h)*WW)*CC;
    #pragma unroll
    for (int j = 0; j < 6; ++j) {
        int co = n0 + j*8 + 2*(lane&3);
        float bx = bias[co], by = bias[co+1];
        *(float2*)(dst + (size_t)w0*CC + co)
            = make_float2(acc[j][0] + bx, acc[j][1] + by);
        *(float2*)(dst + (size_t)(w0+8)*CC + co)
            = make_float2(acc[j][2] + bx, acc[j][3] + by);
    }
}

// ---------------------------------------------------------------------------
// fp16 mma GEMM: C[M,N] = A[M,K] @ B[N,K]^T.  BM=128, BN=64, BK=32.
// 256 threads = 8 warps: warp_m 0..3 (32 M), warp_n 0..1 (32 N).
// A fp32 in gmem (converted on stage), B half in gmem.
// Requires M%128==0, N%64==0, K%32==0.
// ---------------------------------------------------------------------------
#define GAP 40   // smem pitch (halves): 80B = 16*5, conflict-free
__global__ __launch_bounds__(256)
void gemm_f16_k(const float* __restrict__ A, int lda,
                const __half* __restrict__ Bh,
                float* __restrict__ C, int ldc, int K)
{
    __shared__ __half As[128*GAP];
    __shared__ __half Bs[64*GAP];
    const unsigned as_base = (unsigned)__cvta_generic_to_shared(As);
    const unsigned bs_base = (unsigned)__cvta_generic_to_shared(Bs);

    const int tid = threadIdx.x, lane = tid & 31, wid = tid >> 5;
    const int n0 = blockIdx.x*64, m0 = blockIdx.y*128;
    const int warp_m = wid >> 1, warp_n = wid & 1;

    const int a_row = (lane & 15);
    const int a_kof = (lane >> 4) * 8;
    const int b_n   = (lane >> 4) * 8 + (lane & 7);
    const int b_kof = ((lane >> 3) & 1) * 8;

    float acc[2][4][4];
    #pragma unroll
    for (int im = 0; im < 2; ++im)
        #pragma unroll
        for (int in = 0; in < 4; ++in)
            #pragma unroll
            for (int i = 0; i < 4; ++i) acc[im][in][i] = 0.f;

    for (int k0 = 0; k0 < K; k0 += 32) {
        __syncthreads();
        #pragma unroll
        for (int it = 0; it < 4; ++it) {
            int row = it*32 + (tid>>3);
            int kc  = (tid&7)*4;
            float4 v = *(const float4*)(A + (size_t)(m0+row)*lda + k0 + kc);
            __half2* dst = (__half2*)(As + row*GAP + kc);
            dst[0] = __floats2half2_rn(v.x, v.y);
            dst[1] = __floats2half2_rn(v.z, v.w);
        }
        {
            int row = tid >> 2;
            int q   = tid & 3;
            uint4 wv = *(const uint4*)(Bh + (size_t)(n0+row)*K + k0 + q*8);
            *(uint4*)(Bs + row*GAP + q*8) = wv;
        }
        __syncthreads();
        #pragma unroll
        for (int ks = 0; ks < 2; ++ks) {
            unsigned a[2][4];
            #pragma unroll
            for (int im = 0; im < 2; ++im) {
                unsigned addr = as_base +
                    (((warp_m*32 + im*16 + a_row)*GAP + ks*16 + a_kof) << 1);
                ldsm4(a[im][0], a[im][1], a[im][2], a[im][3], addr);
            }
            #pragma unroll
            for (int jp = 0; jp < 2; ++jp) {
                unsigned b0,b1,b2,b3;
                unsigned addr = bs_base +
                    (((warp_n*32 + jp*16 + b_n)*GAP + ks*16 + b_kof) << 1);
                ldsm4(b0,b1,b2,b3, addr);
                #pragma unroll
                for (int im = 0; im < 2; ++im) {
                    mma_f16(acc[im][jp*2+0], a[im][0],a[im][1],a[im][2],a[im][3], b0,b1);
                    mma_f16(acc[im][jp*2+1], a[im][0],a[im][1],a[im][2],a[im][3], b2,b3);
                }
            }
        }
    }

    #pragma unroll
    for (int im = 0; im < 2; ++im) {
        int r = m0 + warp_m*32 + im*16 + (lane>>2);
        #pragma unroll
        for (int in = 0; in < 4; ++in) {
            int c = n0 + warp_n*32 + in*8 + 2*(lane&3);
            *(float2*)(C + (size_t)r*ldc + c)     = make_float2(acc[im][in][0], acc[im][in][1]);
            *(float2*)(C + (size_t)(r+8)*ldc + c) = make_float2(acc[im][in][2], acc[im][in][3]);
        }
    }
}

// ---------------------------------------------------------------------------
// instance-norm statistics
// ---------------------------------------------------------------------------
__global__ void stat_partial_k(const float* __restrict__ y, float2* __restrict__ part) {
    int b = blockIdx.y, ch = blockIdx.x, c = threadIdx.x;   // 192 threads
    const float* src = y + ((size_t)b*LL + (size_t)ch*128)*CC + c;
    float s = 0.f, q = 0.f;
    for (int l = 0; l < 128; ++l) {
        float v = src[(size_t)l*CC];
        s += v; q += v*v;
    }
    part[((size_t)b*128 + ch)*CC + c] = make_float2(s, q);
}

__global__ void stat_final_k(const float2* __restrict__ part, float2* __restrict__ p) {
    int idx = threadIdx.x;            // 384 = BSZ*CC
    int b = idx / CC, c = idx % CC;
    float s = 0.f, q = 0.f;
    for (int k = 0; k < 128; ++k) {
        float2 v = part[((size_t)b*128 + k)*CC + c];
        s += v.x; q += v.y;
    }
    float mu  = s * (1.f/(float)LL);
    float var = q * (1.f/(float)LL) - mu*mu;
    p[idx] = make_float2(mu, rsqrtf(fmaxf(var, 0.f) + EPSV));
}

// xc = instnorm2(y2) + residual(x)
__global__ void apply_nr_k(const float* __restrict__ y2, const float* __restrict__ x,
                           const float2* __restrict__ p, float* __restrict__ xc) {
    size_t i = (size_t)blockIdx.x*256 + threadIdx.x;
    if (i >= (size_t)BL*CC) return;
    int c = (int)(i % CC);
    int b = (int)(i / ((size_t)LL*CC));
    float2 pr = p[b*CC + c];
    xc[i] = (y2[i] - pr.x)*pr.y + x[i];
}

// ---------------------------------------------------------------------------
// LayerNorm over gathered tokens
// ---------------------------------------------------------------------------
__global__ __launch_bounds__(256)
void ln_k(const float* __restrict__ xc, const float* __restrict__ g,
          const float* __restrict__ be, float* __restrict__ xn) {
    int l = blockIdx.x*256 + threadIdx.x;
    int b = blockIdx.y;
    const float* base = xc + (size_t)b*LL*CC;
    float s = 0.f, q = 0.f;
    for (int d = 0; d < CC; ++d) {
        float v = base[(size_t)d*LL + l];
        s += v; q += v*v;
    }
    float mu = s * (1.f/(float)CC);
    float rs = rsqrtf(fmaxf(q*(1.f/(float)CC) - mu*mu, 0.f) + EPSV);
    float* o = xn + ((size_t)b*LL + l)*CC;
    for (int d = 0; d < CC; ++d) {
        float v = base[(size_t)d*LL + l];
        o[d] = (v - mu)*rs*g[d] + be[d];
    }
}

// ---------------------------------------------------------------------------
// fp32 SGEMM (small/odd-shaped projections: x_proj, dt_proj)
// ---------------------------------------------------------------------------
template<int EPI>
__global__ __launch_bounds__(256)
void gemm_k(const float* __restrict__ A, int lda,
            const float* __restrict__ Bw, const float* __restrict__ bias,
            float* __restrict__ C, int ldc, int N, int K)
{
    __shared__ __align__(16) float As[16][68];
    __shared__ __align__(16) float Bs[16][68];

    const int tid = threadIdx.x;
    const int n0 = blockIdx.x * 64, m0 = blockIdx.y * 64;
    const int tm = tid >> 4, tn = tid & 15;
    const int lr = tid >> 2;
    const int lc = (tid & 3) << 2;

    float acc[4][4];
    #pragma unroll
    for (int i = 0; i < 4; ++i)
        #pragma unroll
        for (int j = 0; j < 4; ++j) acc[i][j] = 0.f;

    for (int k0 = 0; k0 < K; k0 += 16) {
        float4 av = make_float4(0.f,0.f,0.f,0.f);
        float4 bv = make_float4(0.f,0.f,0.f,0.f);
        if (k0 + lc < K)
            av = *(const float4*)(A + (size_t)(m0 + lr)*lda + k0 + lc);
        if ((n0 + lr) < N && (k0 + lc) < K)
            bv = *(const float4*)(Bw + (size_t)(n0 + lr)*K + k0 + lc);
        __syncthreads();
        As[lc+0][lr]=av.x; As[lc+1][lr]=av.y; As[lc+2][lr]=av.z; As[lc+3][lr]=av.w;
        Bs[lc+0][lr]=bv.x; Bs[lc+1][lr]=bv.y; Bs[lc+2][lr]=bv.z; Bs[lc+3][lr]=bv.w;
        __syncthreads();
        #pragma unroll
        for (int kk = 0; kk < 16; ++kk) {
            float4 ra = *(const float4*)&As[kk][tm*4];
            float4 rb = *(const float4*)&Bs[kk][tn*4];
            acc[0][0] += ra.x*rb.x; acc[0][1] += ra.x*rb.y; acc[0][2] += ra.x*rb.z; acc[0][3] += ra.x*rb.w;
            acc[1][0] += ra.y*rb.x; acc[1][1] += ra.y*rb.y; acc[1][2] += ra.y*rb.z; acc[1][3] += ra.y*rb.w;
            acc[2][0] += ra.z*rb.x; acc[2][1] += ra.z*rb.y; acc[2][2] += ra.z*rb.z; acc[2][3] += ra.z*rb.w;
            acc[3][0] += ra.w*rb.x; acc[3][1] += ra.w*rb.y; acc[3][2] += ra.w*rb.z; acc[3][3] += ra.w*rb.w;
        }
    }

    #pragma unroll
    for (int i = 0; i < 4; ++i) {
        int m = m0 + tm*4 + i;
        #pragma unroll
        for (int j = 0; j < 4; ++j) {
            int n = n0 + tn*4 + j;
            if (n < N) {
                float v = acc[i][j];
                if (EPI == 1) v = softplusf(v + bias[n]);
                C[(size_t)m*ldc + n] = v;
            }
        }
    }
}

// ---------------------------------------------------------------------------
// causal depthwise conv1d (k=4) + SiLU
// ---------------------------------------------------------------------------
__global__ void dwconv_silu_k(const float* __restrict__ xz, const float* __restrict__ w,
                              const float* __restrict__ bias, float* __restrict__ u) {
    int idx = blockIdx.x*256 + threadIdx.x;
    int b = blockIdx.y;
    int d = idx % DI;
    int l = idx / DI;
    const float* src = xz + (size_t)b*LL*(2*DI) + d;
    float acc = bias[d];
    #pragma unroll
    for (int j = 0; j < 4; ++j) {
        int ll = l - 3 + j;
        if (ll >= 0) acc += src[(size_t)ll*(2*DI)] * w[d*4 + j];
    }
    u[((size_t)b*LL + l)*DI + d] = acc * (1.f/(1.f + __expf(-acc)));
}

// ---------------------------------------------------------------------------
// chunked parallel selective scan
// ---------------------------------------------------------------------------
__global__ __launch_bounds__(256)
void scan_p1_k(const float* __restrict__ dl, const float* __restrict__ ua,
               const float* __restrict__ xdb, const float* __restrict__ alog,
               float2* __restrict__ chk)
{
    int g = blockIdx.x*256 + threadIdx.x;
    int s = g & 15;
    int gc = g >> 4;
    int chunk = gc & (NC - 1);
    int grp = gc >> 6;
    int b = grp / DI;
    int d = grp - b*DI;

    float Av = -__expf(alog[d*DST + s]);
    const int l0 = chunk * CL;
    const float* pdl = dl  + (size_t)b*LL*DI + (size_t)l0*DI + d;
    const float* pu  = ua  + (size_t)b*LL*DI + (size_t)l0*DI + d;
    const float* px  = xdb + (size_t)b*LL*NXDB + (size_t)l0*NXDB;

    float Pa = 1.f, h = 0.f;
    #pragma unroll 4
    for (int l = 0; l < CL; ++l) {
        float delta = pdl[(size_t)l*DI];
        float u     = pu [(size_t)l*DI];
        float Bv    = px[(size_t)l*NXDB + DTR + s];
        float a = __expf(delta*Av);
        Pa *= a;
        h = a*h + (delta*u)*Bv;
    }
    chk[g] = make_float2(Pa, h);
}

__global__ __launch_bounds__(256)
void scan_comb_k(const float2* __restrict__ chk, float* __restrict__ h0)
{
    int gi = blockIdx.x*256 + threadIdx.x;
    if (gi >= NGRP*DST) return;
    int s = gi & 15;
    int grp = gi >> 4;
    float h = 0.f;
    #pragma unroll 8
    for (int c = 0; c < NC; ++c) {
        size_t idx = (((size_t)grp*NC + c) << 4) + s;
        float2 v = chk[idx];
        h0[idx] = h;
        h = v.x*h + v.y;
    }
}

__global__ __launch_bounds__(256)
void scan_p2_k(const float* __restrict__ dl, const float* __restrict__ ua,
               const float* __restrict__ xdb, const float* __restrict__ xz,
               const float* __restrict__ alog, const float* __restrict__ Dpv,
               const float* __restrict__ h0, float* __restrict__ yo)
{
    int g = blockIdx.x*256 + threadIdx.x;
    int s = g & 15;
    int gc = g >> 4;
    int chunk = gc & (NC - 1);
    int grp = gc >> 6;
    int b = grp / DI;
    int d = grp - b*DI;

    float Av = -__expf(alog[d*DST + s]);
    float Dv = Dpv[d];
    const int l0 = chunk * CL;
    const float* pdl = dl  + (size_t)b*LL*DI + (size_t)l0*DI + d;
    const float* pu  = ua  + (size_t)b*LL*DI + (size_t)l0*DI + d;
    const float* px  = xdb + (size_t)b*LL*NXDB + (size_t)l0*NXDB;
    const float* pz  = xz  + (size_t)b*LL*(2*DI) + (size_t)l0*(2*DI) + DI + d;
    float* py        = yo  + (size_t)b*LL*DI + (size_t)l0*DI + d;

    float h = h0[g];
    #pragma unroll 2
    for (int l = 0; l < CL; ++l) {
        float delta = pdl[(size_t)l*DI];
        float u     = pu [(size_t)l*DI];
        float Bv    = px[(size_t)l*NXDB + DTR + s];
        float Cv    = px[(size_t)l*NXDB + DTR + DST + s];
        h = __expf(delta*Av)*h + (delta*u)*Bv;
        float p = h*Cv;
        p += __shfl_xor_sync(0xffffffffu, p, 1);
        p += __shfl_xor_sync(0xffffffffu, p, 2);
        p += __shfl_xor_sync(0xffffffffu, p, 4);
        p += __shfl_xor_sync(0xffffffffu, p, 8);
        if (s == 0) {
            float z = pz[(size_t)l*(2*DI)];
            py[(size_t)l*DI] = (p + u*Dv) * siluf(z);
        }
    }
}

// ---------------------------------------------------------------------------
// launch
// ---------------------------------------------------------------------------
extern "C" void kernel_launch(void* const* d_in, const int* in_sizes, int n_in,
                              void* d_out, int out_size)
{
    (void)in_sizes; (void)n_in; (void)out_size;
    const float* x    = (const float*)d_in[0];
    const float* c1w  = (const float*)d_in[1];
    const float* c1b  = (const float*)d_in[2];
    const float* c2w  = (const float*)d_in[3];
    const float* c2b  = (const float*)d_in[4];
    const float* lng  = (const float*)d_in[5];
    const float* lnb  = (const float*)d_in[6];
    const float* inpw = (const float*)d_in[7];
    const float* c1dw = (const float*)d_in[8];
    const float* c1db = (const float*)d_in[9];
    const float* xpw  = (const float*)d_in[10];
    const float* dtw  = (const float*)d_in[11];
    const float* dtb  = (const float*)d_in[12];
    const float* alog = (const float*)d_in[13];
    const float* Dpv  = (const float*)d_in[14];
    const float* outw = (const float*)d_in[15];
    float* out = (float*)d_out;

    __half *w1h, *w2h, *wih, *woh;
    float *y1, *y2, *xc, *xn, *xz, *ua, *xdb, *dl, *yy, *h0;
    float2 *part, *p1, *p2, *chk;
    cudaGetSymbolAddress((void**)&w1h,  g_w1h);
    cudaGetSymbolAddress((void**)&w2h,  g_w2h);
    cudaGetSymbolAddress((void**)&wih,  g_wih);
    cudaGetSymbolAddress((void**)&woh,  g_woh);
    cudaGetSymbolAddress((void**)&y1,   g_y1);
    cudaGetSymbolAddress((void**)&y2,   g_y2);
    cudaGetSymbolAddress((void**)&xc,   g_xc);
    cudaGetSymbolAddress((void**)&xn,   g_xn);
    cudaGetSymbolAddress((void**)&xz,   g_xz);
    cudaGetSymbolAddress((void**)&ua,   g_ua);
    cudaGetSymbolAddress((void**)&xdb,  g_xdb);
    cudaGetSymbolAddress((void**)&dl,   g_dl);
    cudaGetSymbolAddress((void**)&yy,   g_yy);
    cudaGetSymbolAddress((void**)&part, g_part);
    cudaGetSymbolAddress((void**)&p1,   g_p1);
    cudaGetSymbolAddress((void**)&p2,   g_p2);
    cudaGetSymbolAddress((void**)&chk,  g_chk);
    cudaGetSymbolAddress((void**)&h0,   g_h0);

    cudaFuncSetAttribute(conv_f16_k<false>,
        cudaFuncAttributeMaxDynamicSharedMemorySize, SMEM_CONVH);
    cudaFuncSetAttribute(conv_f16_k<true>,
        cudaFuncAttributeMaxDynamicSharedMemorySize, SMEM_CONVH);

    const int TWB = (27*CC*CC + 255)/256;

    conv_w_half_k<<<TWB, 256>>>(c1w, w1h);
    conv_w_half_k<<<TWB, 256>>>(c2w, w2h);
    proj_w_half_k<<<(2*DI*CC + 255)/256, 256>>>(inpw, wih, 2*DI*CC);
    proj_w_half_k<<<(CC*DI + 255)/256, 256>>>(outw, woh, CC*DI);
    dummy_k<<<1, 32>>>((float*)part);

    // conv1 (fp16 mma + ldmatrix)
    conv_f16_k<false><<<dim3(HH/2, TT, BSZ), 512, SMEM_CONVH>>>(x, w1h, c1b, nullptr, y1);
    stat_partial_k<<<dim3(128, BSZ), 192>>>(y1, part);
    stat_final_k<<<1, BSZ*CC>>>(part, p1);

    // conv2 with fused leaky(instnorm()) on input
    conv_f16_k<true><<<dim3(HH/2, TT, BSZ), 512, SMEM_CONVH>>>(y1, w2h, c2b, p1, y2);
    stat_partial_k<<<dim3(128, BSZ), 192>>>(y2, part);
    stat_final_k<<<1, BSZ*CC>>>(part, p2);
    apply_nr_k<<<(int)(((size_t)BL*CC + 255)/256), 256>>>(y2, x, p2, xc);

    // layernorm over gathered tokens
    ln_k<<<dim3(LL/256, BSZ), 256>>>(xc, lng, lnb, xn);

    // xz = x_norm @ in_proj_w^T   (M=32768, N=768, K=192) fp16 mma
    gemm_f16_k<<<dim3((2*DI)/64, BL/128), 256>>>(xn, CC, wih, xz, 2*DI, CC);

    // depthwise causal conv1d + silu -> u
    dwconv_silu_k<<<dim3((LL*DI)/256, BSZ), 256>>>(xz, c1dw, c1db, ua);

    // xdb = u @ x_proj_w^T        (N=44, K=384) fp32
    gemm_k<0><<<dim3(1, BL/64), 256>>>(ua, DI, xpw, nullptr, xdb, NXDB, NXDB, DI);

    // delta = softplus(dt @ dt_proj_w^T + dt_b) fp32
    gemm_k<1><<<dim3(DI/64, BL/64), 256>>>(xdb, NXDB, dtw, dtb, dl, DI, DI, DTR);

    // chunked parallel selective scan
    scan_p1_k  <<<(NGRP*NC*DST)/256, 256>>>(dl, ua, xdb, alog, chk);
    scan_comb_k<<<(NGRP*DST + 255)/256, 256>>>(chk, h0);
    scan_p2_k  <<<(NGRP*NC*DST)/256, 256>>>(dl, ua, xdb, xz, alog, Dpv, h0, yy);

    // out = y @ out_proj_w^T -> d_out  (N=192, K=384) fp16 mma
    gemm_f16_k<<<dim3(CC/64, BL/128), 256>>>(yy, DI, woh, out, CC, DI);
}